// round 14
// baseline (speedup 1.0000x reference)
#include <cuda_runtime.h>
#include <cstdint>

#define E_  8
#define H_  8
#define D_  512
#define B_  16
#define S_  256
#define DK_ 64

// ---------------- scratch ----------------
__device__ float g_xsum[B_ * D_];
__device__ int   g_sel[B_];
__device__ float g_qh[B_ * H_ * DK_ * S_];          // [b][h][dk][s]
__device__ float g_kh[B_ * H_ * DK_ * S_];          // [b][h][dk][kcol]
__device__ float g_vh[B_ * H_ * S_ * DK_];          // [b][h][s][dk]
__device__ float g_ctx[B_ * S_ * D_];

// ---------------- helpers ----------------
__device__ __forceinline__ uint32_t f2tf32(float x) {
    uint32_t r;
    asm("cvt.rna.tf32.f32 %0, %1;" : "=r"(r) : "f"(x));
    return r;
}

__device__ __forceinline__ void mma_tf32(float* c, const uint32_t* a, const uint32_t* b) {
    asm volatile(
        "mma.sync.aligned.m16n8k8.row.col.f32.tf32.tf32.f32 "
        "{%0,%1,%2,%3}, {%4,%5,%6,%7}, {%8,%9}, {%0,%1,%2,%3};"
        : "+f"(c[0]), "+f"(c[1]), "+f"(c[2]), "+f"(c[3])
        : "r"(a[0]), "r"(a[1]), "r"(a[2]), "r"(a[3]), "r"(b[0]), "r"(b[1]));
}

__device__ __forceinline__ void ldsm_x4(uint32_t* r, uint32_t addr) {
    asm volatile("ldmatrix.sync.aligned.m8n8.x4.shared.b16 {%0,%1,%2,%3}, [%4];"
                 : "=r"(r[0]), "=r"(r[1]), "=r"(r[2]), "=r"(r[3]) : "r"(addr));
}

// packed fp32x2 (Blackwell FFMA2)
__device__ __forceinline__ uint64_t bcast2(float v) {
    uint64_t r;
    asm("mov.b64 %0, {%1,%1};" : "=l"(r) : "f"(v));
    return r;
}
__device__ __forceinline__ void fma2(uint64_t& c, uint64_t a, uint64_t b) {
    asm("fma.rn.f32x2 %0, %1, %2, %0;" : "+l"(c) : "l"(a), "l"(b));
}
__device__ __forceinline__ float2 unpack2(uint64_t v) {
    float2 f;
    asm("mov.b64 {%0,%1}, %2;" : "=f"(f.x), "=f"(f.y) : "l"(v));
    return f;
}
__device__ __forceinline__ float getf4(float4 v, int t) {
    switch (t) {
        case 0: return v.x;
        case 1: return v.y;
        case 2: return v.z;
        default: return v.w;
    }
}

// ---------------- threefry2x32 (JAX partitionable, key=(0,42)) ----------------
__device__ __forceinline__ uint32_t rotl32(uint32_t x, int r) {
    return (x << r) | (x >> (32 - r));
}
__device__ void threefry2x32(uint32_t k0, uint32_t k1, uint32_t c0, uint32_t c1,
                             uint32_t* o0, uint32_t* o1) {
    uint32_t ks2 = k0 ^ k1 ^ 0x1BD11BDAu;
    uint32_t x0 = c0 + k0;
    uint32_t x1 = c1 + k1;
    const int R0[4] = {13, 15, 26, 6};
    const int R1[4] = {17, 29, 16, 24};
#pragma unroll
    for (int i = 0; i < 4; i++) { x0 += x1; x1 = rotl32(x1, R0[i]); x1 ^= x0; }
    x0 += k1;  x1 += ks2 + 1u;
#pragma unroll
    for (int i = 0; i < 4; i++) { x0 += x1; x1 = rotl32(x1, R1[i]); x1 ^= x0; }
    x0 += ks2; x1 += k0 + 2u;
#pragma unroll
    for (int i = 0; i < 4; i++) { x0 += x1; x1 = rotl32(x1, R0[i]); x1 ^= x0; }
    x0 += k0;  x1 += k1 + 3u;
#pragma unroll
    for (int i = 0; i < 4; i++) { x0 += x1; x1 = rotl32(x1, R1[i]); x1 ^= x0; }
    x0 += k1;  x1 += ks2 + 4u;
#pragma unroll
    for (int i = 0; i < 4; i++) { x0 += x1; x1 = rotl32(x1, R0[i]); x1 ^= x0; }
    x0 += ks2; x1 += k0 + 5u;
    *o0 = x0; *o1 = x1;
}

__device__ float erfinv_xla(float x) {
    float w = -log1pf(-x * x);
    float p;
    if (w < 5.0f) {
        w -= 2.5f;
        p = 2.81022636e-08f;
        p = fmaf(p, w, 3.43273939e-07f);
        p = fmaf(p, w, -3.5233877e-06f);
        p = fmaf(p, w, -4.39150654e-06f);
        p = fmaf(p, w, 0.00021858087f);
        p = fmaf(p, w, -0.00125372503f);
        p = fmaf(p, w, -0.00417768164f);
        p = fmaf(p, w, 0.246640727f);
        p = fmaf(p, w, 1.50140941f);
    } else {
        w = sqrtf(w) - 3.0f;
        p = -0.000200214257f;
        p = fmaf(p, w, 0.000100950558f);
        p = fmaf(p, w, 0.00134934322f);
        p = fmaf(p, w, -0.00367342844f);
        p = fmaf(p, w, 0.00573950773f);
        p = fmaf(p, w, -0.0076224613f);
        p = fmaf(p, w, 0.00943887047f);
        p = fmaf(p, w, 1.00167406f);
        p = fmaf(p, w, 2.83297682f);
    }
    return p * x;
}

// ---------------- K1: full xsum ----------------
__global__ void xsum_kernel(const float* __restrict__ q) {
    int b = blockIdx.x, d = threadIdx.x;
    const float* p = q + (size_t)b * S_ * D_ + d;
    float acc = 0.0f;
#pragma unroll 16
    for (int s = 0; s < S_; s++) acc += p[s * D_];
    g_xsum[b * D_ + d] = acc;
}

// ---------------- K2: gating (1024 threads, sliced dot products) ----------------
__global__ __launch_bounds__(1024) void gating_kernel(const float* __restrict__ wg,
                                                      const float* __restrict__ wn,
                                                      float* __restrict__ d_out,
                                                      int out_size) {
    int tid = threadIdx.x;
    int be = tid & 127, slice = tid >> 7;
    int b = be >> 3, e = be & 7;

    float clp = 0.0f, rnp = 0.0f;
#pragma unroll 8
    for (int i = slice * 64; i < slice * 64 + 64; i++) {
        float xs = g_xsum[b * D_ + i];
        clp = fmaf(xs, wg[i * E_ + e], clp);
        rnp = fmaf(xs, wn[i * E_ + e], rnp);
    }

    __shared__ float scl[8][128], srn[8][128];
    __shared__ float s_noisy[128], s_thrin[B_], s_throut[B_];
    __shared__ float s_load[E_], s_imp[E_];
    scl[slice][be] = clp; srn[slice][be] = rnp;
    if (tid < E_) { s_load[tid] = 0.0f; s_imp[tid] = 0.0f; }
    __syncthreads();

    float cl = 0.0f, rn = 0.0f, stdv = 1.0f, noisy = 0.0f;
    if (tid < 128) {
#pragma unroll
        for (int s = 0; s < 8; s++) { cl += scl[s][tid]; rn += srn[s][tid]; }

        float sp = fmaxf(rn, 0.0f) + log1pf(expf(-fabsf(rn)));
        stdv = sp + 0.01f;

        uint32_t o0, o1;
        threefry2x32(0u, 42u, 0u, (uint32_t)tid, &o0, &o1);
        uint32_t bits = o0 ^ o1;
        uint32_t fb = (bits >> 9) | 0x3f800000u;
        float f = __uint_as_float(fb) - 1.0f;
        float u = f * 2.0f + (-0.99999994f);
        u = fmaxf(-0.99999994f, u);
        float z = 1.41421354f * erfinv_xla(u);
        noisy = cl + z * stdv;
        s_noisy[tid] = noisy;
    }
    __syncthreads();

    if (tid < B_) {
        float m1 = -3.0e38f, m2 = -3.0e38f;
        int i1 = 0;
        for (int ee = 0; ee < E_; ee++) {
            float val = s_noisy[tid * 8 + ee];
            if (val > m1) { m2 = m1; m1 = val; i1 = ee; }
            else if (val > m2) { m2 = val; }
        }
        g_sel[tid] = i1;
        s_thrin[tid] = m2;
        s_throut[tid] = m1;
        atomicAdd(&s_imp[i1], 1.0f);
    }
    __syncthreads();

    if (tid < 128) {
        float thr = (noisy > s_thrin[b]) ? s_thrin[b] : s_throut[b];
        float arg = ((cl - thr) / stdv) / 1.41421354f;
        float ph = 0.5f * (1.0f + erff(arg));
        atomicAdd(&s_load[e], ph);
    }
    __syncthreads();

    if (tid == 0) {
        auto cv2 = [](const float* x) {
            float mean = 0.0f;
            for (int i = 0; i < E_; i++) mean += x[i];
            mean *= (1.0f / E_);
            float var = 0.0f;
            for (int i = 0; i < E_; i++) { float d = x[i] - mean; var += d * d; }
            var *= (1.0f / (E_ - 1));
            return var / (mean * mean + 1e-10f);
        };
        float loss = 0.01f * (cv2(s_imp) + cv2(s_load));
        if (out_size > B_ * S_ * D_) d_out[B_ * S_ * D_] = loss;
    }
}

// ---------------- tf32 mma.sync mainloop (128x128 block, K=512), ldmatrix fragments --------
// smem (words): A @0: 128 rows x stride 36 (row-major [m][k])       = 4608
//               B @4608: 128 rows x stride 36 (N-major [n][k])      = 4608
// single buffer, 2 CTAs/SM; fragment loads via ldmatrix (A: x4/mt, B: x4/2nt).
#define SA_ 36
#define SBK_ 36
#define MMA_SMEM_BYTES ((4608 + 4608) * 4)

__device__ __forceinline__ void mma_mainloop(
        uint32_t* sm, const float* __restrict__ A, int lda,
        const float* __restrict__ W, int n0, float acc[4][4][4]) {
    const int tid = threadIdx.x;
    const int wid = tid >> 5, lane = tid & 31;
    const int wm = (wid & 1) * 64, wn = (wid >> 1) * 32;

    // staging indices
    const int arow = tid >> 1, acol = (tid & 1) * 16;   // A: [m][k] rows
    const int bk = tid & 31, bn0 = (tid >> 5) * 16;     // B: lane-per-k, 16 n per thread

    uint32_t* da = sm + arow * SA_ + acol;
    uint32_t* smB = sm + 4608;

    uint32_t smbase;
    asm("{ .reg .u64 t; cvta.to.shared.u64 t, %1; cvt.u32.u64 %0, t; }"
        : "=r"(smbase) : "l"(sm));

    // ldmatrix per-lane base addresses
    const int r8 = lane & 7, sel = lane >> 3;
    const uint32_t a_base = smbase +
        (uint32_t)(((wm + (sel & 1) * 8 + r8) * SA_ + (sel >> 1) * 4) * 4);
    const uint32_t b_base = smbase + (uint32_t)(4608 * 4) +
        (uint32_t)((((wn + (sel >> 1) * 8 + r8) * SBK_) + (sel & 1) * 4) * 4);

    float4 ar[4], br[4];
#pragma unroll
    for (int i = 0; i < 4; i++) {
        ar[i] = *(const float4*)(A + (size_t)arow * lda + acol + 4 * i);
        br[i] = *(const float4*)(W + (size_t)bk * D_ + n0 + bn0 + 4 * i);
    }
#pragma unroll
    for (int i = 0; i < 4; i++) {
        da[4*i+0] = f2tf32(ar[i].x); da[4*i+1] = f2tf32(ar[i].y);
        da[4*i+2] = f2tf32(ar[i].z); da[4*i+3] = f2tf32(ar[i].w);
        float v0 = ar[i].x; (void)v0;
        smB[(bn0 + 4*i + 0) * SBK_ + bk] = f2tf32(br[i].x);
        smB[(bn0 + 4*i + 1) * SBK_ + bk] = f2tf32(br[i].y);
        smB[(bn0 + 4*i + 2) * SBK_ + bk] = f2tf32(br[i].z);
        smB[(bn0 + 4*i + 3) * SBK_ + bk] = f2tf32(br[i].w);
    }
    __syncthreads();

    for (int t = 0; t < 16; t++) {
        if (t < 15) {
            int kb = (t + 1) * 32;
#pragma unroll
            for (int i = 0; i < 4; i++) {
                ar[i] = *(const float4*)(A + (size_t)arow * lda + kb + acol + 4 * i);
                br[i] = *(const float4*)(W + (size_t)(kb + bk) * D_ + n0 + bn0 + 4 * i);
            }
        }
#pragma unroll
        for (int ks = 0; ks < 4; ks++) {
            uint32_t af[4][4], bf[4][2], tmp[4];
#pragma unroll
            for (int mt = 0; mt < 4; mt++)
                ldsm_x4(af[mt], a_base + (uint32_t)((mt * 16 * SA_ + ks * 8) * 4));
            ldsm_x4(tmp, b_base + (uint32_t)((ks * 8) * 4));
            bf[0][0] = tmp[0]; bf[0][1] = tmp[1];
            bf[1][0] = tmp[2]; bf[1][1] = tmp[3];
            ldsm_x4(tmp, b_base + (uint32_t)((16 * SBK_ + ks * 8) * 4));
            bf[2][0] = tmp[0]; bf[2][1] = tmp[1];
            bf[3][0] = tmp[2]; bf[3][1] = tmp[3];
#pragma unroll
            for (int mt = 0; mt < 4; mt++)
#pragma unroll
                for (int nt = 0; nt < 4; nt++)
                    mma_tf32(acc[mt][nt], af[mt], bf[nt]);
        }
        if (t < 15) {
            __syncthreads();   // all fragment reads complete
#pragma unroll
            for (int i = 0; i < 4; i++) {
                da[4*i+0] = f2tf32(ar[i].x); da[4*i+1] = f2tf32(ar[i].y);
                da[4*i+2] = f2tf32(ar[i].z); da[4*i+3] = f2tf32(ar[i].w);
                smB[(bn0 + 4*i + 0) * SBK_ + bk] = f2tf32(br[i].x);
                smB[(bn0 + 4*i + 1) * SBK_ + bk] = f2tf32(br[i].y);
                smB[(bn0 + 4*i + 2) * SBK_ + bk] = f2tf32(br[i].z);
                smB[(bn0 + 4*i + 3) * SBK_ + bk] = f2tf32(br[i].w);
            }
            __syncthreads();   // buffer refilled
        }
    }
}

// ---------------- K3: projections via mma.sync tf32 ----------------
__global__ __launch_bounds__(256, 2) void proj_mma(
        const float* __restrict__ q, const float* __restrict__ k,
        const float* __restrict__ v,
        const float* __restrict__ wq, const float* __restrict__ wk,
        const float* __restrict__ wv,
        const float* __restrict__ bq, const float* __restrict__ bk,
        const float* __restrict__ bv) {
    extern __shared__ uint32_t smu[];
    int z = blockIdx.z;
    int b = z / 3, p = z % 3;
    int e = g_sel[b];
    const float* X = (p == 0 ? q : (p == 1 ? k : v)) + (size_t)b * S_ * D_;
    const float* W = (p == 0 ? wq : (p == 1 ? wk : wv)) + (size_t)e * D_ * D_;
    const float* bias = (p == 0 ? bq : (p == 1 ? bk : bv)) + e * D_;
    float* Out = (p == 0 ? g_qh : (p == 1 ? g_kh : g_vh));
    int bn = blockIdx.x * 128, m0 = blockIdx.y * 128;

    float acc[4][4][4] = {};
    mma_mainloop(smu, X + (size_t)m0 * D_, D_, W, bn, acc);

    const int lane = threadIdx.x & 31, wid = threadIdx.x >> 5;
    const int wm = (wid & 1) * 64, wn = (wid >> 1) * 32;
    const int group = lane >> 2, tig = lane & 3;

#pragma unroll
    for (int mt = 0; mt < 4; mt++) {
#pragma unroll
        for (int nt = 0; nt < 4; nt++) {
            int n = bn + wn + nt * 8 + 2 * tig;
            int m = m0 + wm + mt * 16 + group;
            int h = n >> 6, dk = n & 63;
            float b0v = bias[n], b1v = bias[n + 1];
            if (p < 2) {
                size_t base = ((size_t)(b * H_ + h) * DK_ + dk) * S_;
                Out[base + m]            = acc[mt][nt][0] + b0v;
                Out[base + S_ + m]       = acc[mt][nt][1] + b1v;
                Out[base + m + 8]        = acc[mt][nt][2] + b0v;
                Out[base + S_ + m + 8]   = acc[mt][nt][3] + b1v;
            } else {
                size_t base = ((size_t)(b * H_ + h) * S_ + m) * DK_ + dk;
                Out[base]                = acc[mt][nt][0] + b0v;
                Out[base + 1]            = acc[mt][nt][1] + b1v;
                Out[base + 8 * DK_]      = acc[mt][nt][2] + b0v;
                Out[base + 8 * DK_ + 1]  = acc[mt][nt][3] + b1v;
            }
        }
    }
}

// ---------------- K5: final projection via mma.sync tf32 ----------------
__global__ __launch_bounds__(256, 2) void final_mma(const float* __restrict__ wo,
                                                    const float* __restrict__ bo,
                                                    float* __restrict__ out) {
    extern __shared__ uint32_t smu[];
    int b = blockIdx.z;
    int e = g_sel[b];
    const float* A = g_ctx + (size_t)b * S_ * D_;
    const float* W = wo + (size_t)e * D_ * D_;
    const float* bias = bo + e * D_;
    int bn = blockIdx.x * 128, m0 = blockIdx.y * 128;

    float acc[4][4][4] = {};
    mma_mainloop(smu, A + (size_t)m0 * D_, D_, W, bn, acc);

    const int lane = threadIdx.x & 31, wid = threadIdx.x >> 5;
    const int wm = (wid & 1) * 64, wn = (wid >> 1) * 32;
    const int group = lane >> 2, tig = lane & 3;

#pragma unroll
    for (int mt = 0; mt < 4; mt++) {
#pragma unroll
        for (int nt = 0; nt < 4; nt++) {
            int n = bn + wn + nt * 8 + 2 * tig;
            int m = m0 + wm + mt * 16 + group;
            float b0v = bias[n], b1v = bias[n + 1];
            float* d0 = out + ((size_t)b * S_ + m) * D_ + n;
            d0[0]            = acc[mt][nt][0] + b0v;
            d0[1]            = acc[mt][nt][1] + b1v;
            d0[8 * D_]       = acc[mt][nt][2] + b0v;
            d0[8 * D_ + 1]   = acc[mt][nt][3] + b1v;
        }
    }
}

// ---------------- K4: fused attention (R9/R12 config: 64-row q-tiles, streamed K/V) --------
#define ATTN_SMEM_BYTES (28672 * 4)

__global__ __launch_bounds__(256, 2) void fused_attn_kernel(const int* __restrict__ mask) {
    extern __shared__ float smf[];
    float* Qt = smf;
    float* Ps = smf + 12288;

    int z = blockIdx.x;
    int bh = z >> 2, qt = z & 3;
    int b = bh >> 3, h = bh & 7;
    int tid = threadIdx.x;
    int warp = tid >> 5, lane = tid & 31;

    const float* ksrc = g_kh + (size_t)bh * 16384;   // [dk][256]
    const float* vsrc = g_vh + (size_t)bh * 16384;   // [256][64]
    const float* qsrc = g_qh + (size_t)bh * 16384 + qt * 64;

    // load Qt[dk][0..63]
    {
#pragma unroll
        for (int j = 0; j < 4; j++) {
            int lin = tid + j * 256;
            int dk = lin >> 4, c = (lin & 15) * 4;
            *(float4*)&Qt[dk * 64 + c] = *(const float4*)(qsrc + (size_t)dk * S_ + c);
        }
    }

    // preload K chunk 0 into Buf0
    {
        float* dst = smf + 4096;
#pragma unroll
        for (int j = 0; j < 4; j++) {
            int lin = tid + j * 256;
            int dk = lin >> 4, c = (lin & 15) * 4;
            *(float4*)&dst[dk * 64 + c] = *(const float4*)(ksrc + (size_t)dk * S_ + c);
        }
    }
    __syncthreads();

    // -------- GEMM1: scores over 4 K-chunks --------
    float pf[8][8];
    for (int ch = 0; ch < 4; ch++) {
        float4 nx[4];
        if (ch < 3) {
#pragma unroll
            for (int j = 0; j < 4; j++) {
                int lin = tid + j * 256;
                int dk = lin >> 4, c = (lin & 15) * 4;
                nx[j] = *(const float4*)(ksrc + (size_t)dk * S_ + (ch + 1) * 64 + c);
            }
        }
        const float* cur = smf + 4096 + (ch & 1) * 4096;

        uint64_t pch[8] = {};
        {
            float4 x0 = *(const float4*)&Qt[warp * 8];
            float4 x1 = *(const float4*)&Qt[warp * 8 + 4];
            uint64_t kk = *(const uint64_t*)&cur[lane * 2];
#pragma unroll 8
            for (int dk = 0; dk < 64; dk++) {
                float a[8] = {x0.x, x0.y, x0.z, x0.w, x1.x, x1.y, x1.z, x1.w};
                uint64_t kc = kk;
                if (dk < 63) {
                    x0 = *(const float4*)&Qt[(dk + 1) * 64 + warp * 8];
                    x1 = *(const float4*)&Qt[(dk + 1) * 64 + warp * 8 + 4];
                    kk = *(const uint64_t*)&cur[(dk + 1) * 64 + lane * 2];
                }
#pragma unroll
                for (int i = 0; i < 8; i++) fma2(pch[i], bcast2(a[i]), kc);
            }
        }
#pragma unroll
        for (int i = 0; i < 8; i++) {
            float2 f = unpack2(pch[i]);
            pf[i][2 * ch]     = f.x;
            pf[i][2 * ch + 1] = f.y;
        }

        if (ch < 3) {
            float* nb = smf + 4096 + ((ch + 1) & 1) * 4096;
#pragma unroll
            for (int j = 0; j < 4; j++) {
                int lin = tid + j * 256;
                int dk = lin >> 4, c = (lin & 15) * 4;
                *(float4*)&nb[dk * 64 + c] = nx[j];
            }
        }
        __syncthreads();
    }

    // -------- mask + softmax --------
#pragma unroll
    for (int i = 0; i < 8; i++) {
        int r = qt * 64 + warp * 8 + i;
#pragma unroll
        for (int c = 0; c < 4; c++) {
            int2 mm = *(const int2*)&mask[r * S_ + c * 64 + lane * 2];
            pf[i][2 * c]     = (mm.x == 0) ? -1e9f : pf[i][2 * c]     * 0.125f;
            pf[i][2 * c + 1] = (mm.y == 0) ? -1e9f : pf[i][2 * c + 1] * 0.125f;
        }
        float mx = pf[i][0];
#pragma unroll
        for (int j = 1; j < 8; j++) mx = fmaxf(mx, pf[i][j]);
#pragma unroll
        for (int off = 16; off > 0; off >>= 1)
            mx = fmaxf(mx, __shfl_xor_sync(0xffffffffu, mx, off));
        float sum = 0.0f;
#pragma unroll
        for (int j = 0; j < 8; j++) { pf[i][j] = __expf(pf[i][j] - mx); sum += pf[i][j]; }
#pragma unroll
        for (int off = 16; off > 0; off >>= 1)
            sum += __shfl_xor_sync(0xffffffffu, sum, off);
        float inv = 1.0f / sum;
#pragma unroll
        for (int j = 0; j < 8; j++) pf[i][j] *= inv;
    }

    // write Ps[row][col]
#pragma unroll
    for (int i = 0; i < 8; i++) {
        int row = warp * 8 + i;
#pragma unroll
        for (int c = 0; c < 4; c++) {
            *(float2*)&Ps[row * 256 + c * 64 + lane * 2] =
                make_float2(pf[i][2 * c], pf[i][2 * c + 1]);
        }
    }

    // preload V chunk 0 into Buf0
    {
        float4* dst = (float4*)(smf + 4096);
        const float4* src = (const float4*)vsrc;
#pragma unroll
        for (int j = 0; j < 4; j++) dst[tid + j * 256] = src[tid + j * 256];
    }
    __syncthreads();

    // -------- GEMM2: ctx = Ps @ V over 4 V-chunks --------
    const int ty2 = tid >> 4, tx2 = tid & 15;
    uint64_t c2p[4][2] = {};
    for (int ch = 0; ch < 4; ch++) {
        float4 nv[4];
        if (ch < 3) {
            const float4* src = (const float4*)(vsrc + (ch + 1) * 4096);
#pragma unroll
            for (int j = 0; j < 4; j++) nv[j] = src[tid + j * 256];
        }
        const float* Vb = smf + 4096 + (ch & 1) * 4096;

        {
            float4 av[2][4];
            uint64_t bvu[2][4][2];
#pragma unroll
            for (int i = 0; i < 4; i++)
                av[0][i] = *(const float4*)&Ps[(ty2 * 4 + i) * 256 + ch * 64];
#pragma unroll
            for (int t = 0; t < 4; t++) {
                const uint64_t* vp = (const uint64_t*)&Vb[t * 64 + tx2 * 4];
                bvu[0][t][0] = vp[0]; bvu[0][t][1] = vp[1];
            }
#pragma unroll 2
            for (int kc = 0; kc < 64; kc += 4) {
                int curb = (kc >> 2) & 1, nxt = curb ^ 1;
                if (kc < 60) {
#pragma unroll
                    for (int i = 0; i < 4; i++)
                        av[nxt][i] = *(const float4*)&Ps[(ty2 * 4 + i) * 256 + ch * 64 + kc + 4];
#pragma unroll
                    for (int t = 0; t < 4; t++) {
                        const uint64_t* vp = (const uint64_t*)&Vb[(kc + 4 + t) * 64 + tx2 * 4];
                        bvu[nxt][t][0] = vp[0]; bvu[nxt][t][1] = vp[1];
                    }
                }
#pragma unroll
                for (int t = 0; t < 4; t++) {
#pragma unroll
                    for (int i = 0; i < 4; i++) {
                        uint64_t ap = bcast2(getf4(av[curb][i], t));
                        fma2(c2p[i][0], ap, bvu[curb][t][0]);
                        fma2(c2p[i][1], ap, bvu[curb][t][1]);
                    }
                }
            }
        }

        if (ch < 3) {
            float* nb = smf + 4096 + ((ch + 1) & 1) * 4096;
            float4* dst = (float4*)nb;
#pragma unroll
            for (int j = 0; j < 4; j++) dst[tid + j * 256] = nv[j];
        }
        __syncthreads();
    }

    // write ctx
#pragma unroll
    for (int i = 0; i < 4; i++) {
        int s = qt * 64 + ty2 * 4 + i;
        float2 lo = unpack2(c2p[i][0]);
        float2 hi = unpack2(c2p[i][1]);
        *(float4*)&g_ctx[((size_t)b * S_ + s) * D_ + h * DK_ + tx2 * 4] =
            make_float4(lo.x, lo.y, hi.x, hi.y);
    }
}

// ---------------- launch ----------------
extern "C" void kernel_launch(void* const* d_in, const int* in_sizes, int n_in,
                              void* d_out, int out_size) {
    const float* q    = (const float*)d_in[0];
    const float* k    = (const float*)d_in[1];
    const float* v    = (const float*)d_in[2];
    const int*   mask = (const int*)  d_in[3];
    const float* wg   = (const float*)d_in[4];
    const float* wn   = (const float*)d_in[5];
    const float* wq   = (const float*)d_in[6];
    const float* bq   = (const float*)d_in[7];
    const float* wk   = (const float*)d_in[8];
    const float* bk   = (const float*)d_in[9];
    const float* wv   = (const float*)d_in[10];
    const float* bv   = (const float*)d_in[11];
    const float* wo   = (const float*)d_in[12];
    const float* bo   = (const float*)d_in[13];
    float* out = (float*)d_out;

    cudaFuncSetAttribute(fused_attn_kernel,
                         cudaFuncAttributeMaxDynamicSharedMemorySize, ATTN_SMEM_BYTES);
    cudaFuncSetAttribute(proj_mma,
                         cudaFuncAttributeMaxDynamicSharedMemorySize, MMA_SMEM_BYTES);
    cudaFuncSetAttribute(final_mma,
                         cudaFuncAttributeMaxDynamicSharedMemorySize, MMA_SMEM_BYTES);

    xsum_kernel<<<B_, 512>>>(q);
    gating_kernel<<<1, 1024>>>(wg, wn, out, out_size);
    proj_mma<<<dim3(4, 2, B_ * 3), 256, MMA_SMEM_BYTES>>>(q, k, v, wq, wk, wv, bq, bk, bv);
    fused_attn_kernel<<<B_ * H_ * 4, 256, ATTN_SMEM_BYTES>>>(mask);
    final_mma<<<dim3(4, 2, B_), 256, MMA_SMEM_BYTES>>>(wo, bo, out);
}

// round 15
// speedup vs baseline: 1.3035x; 1.3035x over previous
#include <cuda_runtime.h>
#include <cstdint>

#define E_  8
#define H_  8
#define D_  512
#define B_  16
#define S_  256
#define DK_ 64

// ---------------- scratch ----------------
__device__ float g_xsum[B_ * D_];
__device__ int   g_sel[B_];
__device__ float g_qh[B_ * H_ * DK_ * S_];          // [b][h][dk][s]
__device__ float g_kh[B_ * H_ * DK_ * S_];          // [b][h][dk][kcol]
__device__ float g_vh[B_ * H_ * S_ * DK_];          // [b][h][s][dk]
__device__ float g_ctx[B_ * S_ * D_];

// ---------------- helpers ----------------
// pack two fp32 -> fp16x2 (lo = first arg), round-to-nearest
__device__ __forceinline__ uint32_t f2h2(float lo, float hi) {
    uint32_t r;
    asm("cvt.rn.f16x2.f32 %0, %1, %2;" : "=r"(r) : "f"(hi), "f"(lo));
    return r;
}

__device__ __forceinline__ void mma_f16(float* c, const uint32_t* a, const uint32_t* b) {
    asm volatile(
        "mma.sync.aligned.m16n8k16.row.col.f32.f16.f16.f32 "
        "{%0,%1,%2,%3}, {%4,%5,%6,%7}, {%8,%9}, {%0,%1,%2,%3};"
        : "+f"(c[0]), "+f"(c[1]), "+f"(c[2]), "+f"(c[3])
        : "r"(a[0]), "r"(a[1]), "r"(a[2]), "r"(a[3]), "r"(b[0]), "r"(b[1]));
}

// packed fp32x2 (Blackwell FFMA2)
__device__ __forceinline__ uint64_t bcast2(float v) {
    uint64_t r;
    asm("mov.b64 %0, {%1,%1};" : "=l"(r) : "f"(v));
    return r;
}
__device__ __forceinline__ void fma2(uint64_t& c, uint64_t a, uint64_t b) {
    asm("fma.rn.f32x2 %0, %1, %2, %0;" : "+l"(c) : "l"(a), "l"(b));
}
__device__ __forceinline__ float2 unpack2(uint64_t v) {
    float2 f;
    asm("mov.b64 {%0,%1}, %2;" : "=f"(f.x), "=f"(f.y) : "l"(v));
    return f;
}
__device__ __forceinline__ float getf4(float4 v, int t) {
    switch (t) {
        case 0: return v.x;
        case 1: return v.y;
        case 2: return v.z;
        default: return v.w;
    }
}

// ---------------- threefry2x32 (JAX partitionable, key=(0,42)) ----------------
__device__ __forceinline__ uint32_t rotl32(uint32_t x, int r) {
    return (x << r) | (x >> (32 - r));
}
__device__ void threefry2x32(uint32_t k0, uint32_t k1, uint32_t c0, uint32_t c1,
                             uint32_t* o0, uint32_t* o1) {
    uint32_t ks2 = k0 ^ k1 ^ 0x1BD11BDAu;
    uint32_t x0 = c0 + k0;
    uint32_t x1 = c1 + k1;
    const int R0[4] = {13, 15, 26, 6};
    const int R1[4] = {17, 29, 16, 24};
#pragma unroll
    for (int i = 0; i < 4; i++) { x0 += x1; x1 = rotl32(x1, R0[i]); x1 ^= x0; }
    x0 += k1;  x1 += ks2 + 1u;
#pragma unroll
    for (int i = 0; i < 4; i++) { x0 += x1; x1 = rotl32(x1, R1[i]); x1 ^= x0; }
    x0 += ks2; x1 += k0 + 2u;
#pragma unroll
    for (int i = 0; i < 4; i++) { x0 += x1; x1 = rotl32(x1, R0[i]); x1 ^= x0; }
    x0 += k0;  x1 += k1 + 3u;
#pragma unroll
    for (int i = 0; i < 4; i++) { x0 += x1; x1 = rotl32(x1, R1[i]); x1 ^= x0; }
    x0 += k1;  x1 += ks2 + 4u;
#pragma unroll
    for (int i = 0; i < 4; i++) { x0 += x1; x1 = rotl32(x1, R0[i]); x1 ^= x0; }
    x0 += ks2; x1 += k0 + 5u;
    *o0 = x0; *o1 = x1;
}

__device__ float erfinv_xla(float x) {
    float w = -log1pf(-x * x);
    float p;
    if (w < 5.0f) {
        w -= 2.5f;
        p = 2.81022636e-08f;
        p = fmaf(p, w, 3.43273939e-07f);
        p = fmaf(p, w, -3.5233877e-06f);
        p = fmaf(p, w, -4.39150654e-06f);
        p = fmaf(p, w, 0.00021858087f);
        p = fmaf(p, w, -0.00125372503f);
        p = fmaf(p, w, -0.00417768164f);
        p = fmaf(p, w, 0.246640727f);
        p = fmaf(p, w, 1.50140941f);
    } else {
        w = sqrtf(w) - 3.0f;
        p = -0.000200214257f;
        p = fmaf(p, w, 0.000100950558f);
        p = fmaf(p, w, 0.00134934322f);
        p = fmaf(p, w, -0.00367342844f);
        p = fmaf(p, w, 0.00573950773f);
        p = fmaf(p, w, -0.0076224613f);
        p = fmaf(p, w, 0.00943887047f);
        p = fmaf(p, w, 1.00167406f);
        p = fmaf(p, w, 2.83297682f);
    }
    return p * x;
}

// ---------------- K1: full xsum ----------------
__global__ void xsum_kernel(const float* __restrict__ q) {
    int b = blockIdx.x, d = threadIdx.x;
    const float* p = q + (size_t)b * S_ * D_ + d;
    float acc = 0.0f;
#pragma unroll 16
    for (int s = 0; s < S_; s++) acc += p[s * D_];
    g_xsum[b * D_ + d] = acc;
}

// ---------------- K2: gating (1024 threads, sliced dot products) ----------------
__global__ __launch_bounds__(1024) void gating_kernel(const float* __restrict__ wg,
                                                      const float* __restrict__ wn,
                                                      float* __restrict__ d_out,
                                                      int out_size) {
    int tid = threadIdx.x;
    int be = tid & 127, slice = tid >> 7;
    int b = be >> 3, e = be & 7;

    float clp = 0.0f, rnp = 0.0f;
#pragma unroll 8
    for (int i = slice * 64; i < slice * 64 + 64; i++) {
        float xs = g_xsum[b * D_ + i];
        clp = fmaf(xs, wg[i * E_ + e], clp);
        rnp = fmaf(xs, wn[i * E_ + e], rnp);
    }

    __shared__ float scl[8][128], srn[8][128];
    __shared__ float s_noisy[128], s_thrin[B_], s_throut[B_];
    __shared__ float s_load[E_], s_imp[E_];
    scl[slice][be] = clp; srn[slice][be] = rnp;
    if (tid < E_) { s_load[tid] = 0.0f; s_imp[tid] = 0.0f; }
    __syncthreads();

    float cl = 0.0f, rn = 0.0f, stdv = 1.0f, noisy = 0.0f;
    if (tid < 128) {
#pragma unroll
        for (int s = 0; s < 8; s++) { cl += scl[s][tid]; rn += srn[s][tid]; }

        float sp = fmaxf(rn, 0.0f) + log1pf(expf(-fabsf(rn)));
        stdv = sp + 0.01f;

        uint32_t o0, o1;
        threefry2x32(0u, 42u, 0u, (uint32_t)tid, &o0, &o1);
        uint32_t bits = o0 ^ o1;
        uint32_t fb = (bits >> 9) | 0x3f800000u;
        float f = __uint_as_float(fb) - 1.0f;
        float u = f * 2.0f + (-0.99999994f);
        u = fmaxf(-0.99999994f, u);
        float z = 1.41421354f * erfinv_xla(u);
        noisy = cl + z * stdv;
        s_noisy[tid] = noisy;
    }
    __syncthreads();

    if (tid < B_) {
        float m1 = -3.0e38f, m2 = -3.0e38f;
        int i1 = 0;
        for (int ee = 0; ee < E_; ee++) {
            float val = s_noisy[tid * 8 + ee];
            if (val > m1) { m2 = m1; m1 = val; i1 = ee; }
            else if (val > m2) { m2 = val; }
        }
        g_sel[tid] = i1;
        s_thrin[tid] = m2;
        s_throut[tid] = m1;
        atomicAdd(&s_imp[i1], 1.0f);
    }
    __syncthreads();

    if (tid < 128) {
        float thr = (noisy > s_thrin[b]) ? s_thrin[b] : s_throut[b];
        float arg = ((cl - thr) / stdv) / 1.41421354f;
        float ph = 0.5f * (1.0f + erff(arg));
        atomicAdd(&s_load[e], ph);
    }
    __syncthreads();

    if (tid == 0) {
        auto cv2 = [](const float* x) {
            float mean = 0.0f;
            for (int i = 0; i < E_; i++) mean += x[i];
            mean *= (1.0f / E_);
            float var = 0.0f;
            for (int i = 0; i < E_; i++) { float d = x[i] - mean; var += d * d; }
            var *= (1.0f / (E_ - 1));
            return var / (mean * mean + 1e-10f);
        };
        float loss = 0.01f * (cv2(s_imp) + cv2(s_load));
        if (out_size > B_ * S_ * D_) d_out[B_ * S_ * D_] = loss;
    }
}

// ---------------- fp16 mma.sync mainloop (128x128 block, K=512) ----------------
// smem words: A @0: [128 m] x stride 20 (16 half2 per row + pad 4)  = 2560
//             B2 @2560: [16 kp] x stride 136 (128 half2 + pad 8)    = 2176
// total 18944 B, single buffer, 2 CTAs/SM.
#define SAH_ 20
#define SBH_ 136
#define MMA_SMEM_BYTES ((2560 + 2176) * 4)

__device__ __forceinline__ void mma_mainloop(
        uint32_t* sm, const float* __restrict__ A, int lda,
        const float* __restrict__ W, int n0, float acc[4][4][4]) {
    const int tid = threadIdx.x;
    const int wid = tid >> 5, lane = tid & 31;
    const int wm = (wid & 1) * 64, wn = (wid >> 1) * 32;
    const int group = lane >> 2, tig = lane & 3;

    // staging indices
    const int arow = tid >> 1, acw = (tid & 1) * 8;   // A: row, word offset (8 half2 = 16 floats)
    const int kp = tid >> 4, nb = (tid & 15) * 8;     // B: k-pair, 8 n per thread

    uint32_t* da = sm + arow * SAH_ + acw;
    uint32_t* smB = sm + 2560;
    const uint32_t* As = sm;
    const uint32_t* Bs = smB;

    float4 ar[4];          // A: 16 floats of this thread's row chunk
    float4 b0a, b0b, b1a, b1b;   // B: rows 2kp, 2kp+1, 8 floats each
#pragma unroll
    for (int i = 0; i < 4; i++)
        ar[i] = *(const float4*)(A + (size_t)arow * lda + acw * 2 + 4 * i);
    {
        const float* Wr0 = W + (size_t)(2 * kp) * D_ + n0 + nb;
        const float* Wr1 = Wr0 + D_;
        b0a = *(const float4*)(Wr0);     b0b = *(const float4*)(Wr0 + 4);
        b1a = *(const float4*)(Wr1);     b1b = *(const float4*)(Wr1 + 4);
    }
#pragma unroll
    for (int i = 0; i < 4; i++) {
        da[2*i]   = f2h2(getf4(ar[i], 0), getf4(ar[i], 1));
        da[2*i+1] = f2h2(getf4(ar[i], 2), getf4(ar[i], 3));
    }
    {
        uint32_t* dbb = smB + kp * SBH_ + nb;
#pragma unroll
        for (int j = 0; j < 4; j++) dbb[j]     = f2h2(getf4(b0a, j), getf4(b1a, j));
#pragma unroll
        for (int j = 0; j < 4; j++) dbb[4 + j] = f2h2(getf4(b0b, j), getf4(b1b, j));
    }
    __syncthreads();

    for (int t = 0; t < 16; t++) {
        if (t < 15) {
            int kb = (t + 1) * 32;
#pragma unroll
            for (int i = 0; i < 4; i++)
                ar[i] = *(const float4*)(A + (size_t)arow * lda + kb + acw * 2 + 4 * i);
            const float* Wr0 = W + (size_t)(kb + 2 * kp) * D_ + n0 + nb;
            const float* Wr1 = Wr0 + D_;
            b0a = *(const float4*)(Wr0);     b0b = *(const float4*)(Wr0 + 4);
            b1a = *(const float4*)(Wr1);     b1b = *(const float4*)(Wr1 + 4);
        }
#pragma unroll
        for (int ks = 0; ks < 2; ks++) {
            uint32_t af[4][4], bf[4][2];
#pragma unroll
            for (int mt = 0; mt < 4; mt++) {
                int r0 = wm + mt * 16 + group;
                af[mt][0] = As[r0 * SAH_ + ks * 8 + tig];
                af[mt][1] = As[(r0 + 8) * SAH_ + ks * 8 + tig];
                af[mt][2] = As[r0 * SAH_ + ks * 8 + tig + 4];
                af[mt][3] = As[(r0 + 8) * SAH_ + ks * 8 + tig + 4];
            }
#pragma unroll
            for (int nt = 0; nt < 4; nt++) {
                int c0 = wn + nt * 8 + group;
                bf[nt][0] = Bs[(ks * 8 + tig) * SBH_ + c0];
                bf[nt][1] = Bs[(ks * 8 + tig + 4) * SBH_ + c0];
            }
#pragma unroll
            for (int mt = 0; mt < 4; mt++)
#pragma unroll
                for (int nt = 0; nt < 4; nt++)
                    mma_f16(acc[mt][nt], af[mt], bf[nt]);
        }
        if (t < 15) {
            __syncthreads();   // all fragment reads of the buffer complete
#pragma unroll
            for (int i = 0; i < 4; i++) {
                da[2*i]   = f2h2(getf4(ar[i], 0), getf4(ar[i], 1));
                da[2*i+1] = f2h2(getf4(ar[i], 2), getf4(ar[i], 3));
            }
            uint32_t* dbb = smB + kp * SBH_ + nb;
#pragma unroll
            for (int j = 0; j < 4; j++) dbb[j]     = f2h2(getf4(b0a, j), getf4(b1a, j));
#pragma unroll
            for (int j = 0; j < 4; j++) dbb[4 + j] = f2h2(getf4(b0b, j), getf4(b1b, j));
            __syncthreads();   // buffer refilled
        }
    }
}

// ---------------- K3: projections via mma.sync fp16 ----------------
__global__ __launch_bounds__(256, 2) void proj_mma(
        const float* __restrict__ q, const float* __restrict__ k,
        const float* __restrict__ v,
        const float* __restrict__ wq, const float* __restrict__ wk,
        const float* __restrict__ wv,
        const float* __restrict__ bq, const float* __restrict__ bk,
        const float* __restrict__ bv) {
    extern __shared__ uint32_t smu[];
    int z = blockIdx.z;
    int b = z / 3, p = z % 3;
    int e = g_sel[b];
    const float* X = (p == 0 ? q : (p == 1 ? k : v)) + (size_t)b * S_ * D_;
    const float* W = (p == 0 ? wq : (p == 1 ? wk : wv)) + (size_t)e * D_ * D_;
    const float* bias = (p == 0 ? bq : (p == 1 ? bk : bv)) + e * D_;
    float* Out = (p == 0 ? g_qh : (p == 1 ? g_kh : g_vh));
    int bn = blockIdx.x * 128, m0 = blockIdx.y * 128;

    float acc[4][4][4] = {};
    mma_mainloop(smu, X + (size_t)m0 * D_, D_, W, bn, acc);

    const int lane = threadIdx.x & 31, wid = threadIdx.x >> 5;
    const int wm = (wid & 1) * 64, wn = (wid >> 1) * 32;
    const int group = lane >> 2, tig = lane & 3;

#pragma unroll
    for (int mt = 0; mt < 4; mt++) {
#pragma unroll
        for (int nt = 0; nt < 4; nt++) {
            int n = bn + wn + nt * 8 + 2 * tig;
            int m = m0 + wm + mt * 16 + group;
            int h = n >> 6, dk = n & 63;
            float b0v = bias[n], b1v = bias[n + 1];
            if (p < 2) {
                size_t base = ((size_t)(b * H_ + h) * DK_ + dk) * S_;
                Out[base + m]            = acc[mt][nt][0] + b0v;
                Out[base + S_ + m]       = acc[mt][nt][1] + b1v;
                Out[base + m + 8]        = acc[mt][nt][2] + b0v;
                Out[base + S_ + m + 8]   = acc[mt][nt][3] + b1v;
            } else {
                size_t base = ((size_t)(b * H_ + h) * S_ + m) * DK_ + dk;
                Out[base]                = acc[mt][nt][0] + b0v;
                Out[base + 1]            = acc[mt][nt][1] + b1v;
                Out[base + 8 * DK_]      = acc[mt][nt][2] + b0v;
                Out[base + 8 * DK_ + 1]  = acc[mt][nt][3] + b1v;
            }
        }
    }
}

// ---------------- K5: final projection via mma.sync fp16 ----------------
__global__ __launch_bounds__(256, 2) void final_mma(const float* __restrict__ wo,
                                                    const float* __restrict__ bo,
                                                    float* __restrict__ out) {
    extern __shared__ uint32_t smu[];
    int b = blockIdx.z;
    int e = g_sel[b];
    const float* A = g_ctx + (size_t)b * S_ * D_;
    const float* W = wo + (size_t)e * D_ * D_;
    const float* bias = bo + e * D_;
    int bn = blockIdx.x * 128, m0 = blockIdx.y * 128;

    float acc[4][4][4] = {};
    mma_mainloop(smu, A + (size_t)m0 * D_, D_, W, bn, acc);

    const int lane = threadIdx.x & 31, wid = threadIdx.x >> 5;
    const int wm = (wid & 1) * 64, wn = (wid >> 1) * 32;
    const int group = lane >> 2, tig = lane & 3;

#pragma unroll
    for (int mt = 0; mt < 4; mt++) {
#pragma unroll
        for (int nt = 0; nt < 4; nt++) {
            int n = bn + wn + nt * 8 + 2 * tig;
            int m = m0 + wm + mt * 16 + group;
            float b0v = bias[n], b1v = bias[n + 1];
            float* d0 = out + ((size_t)b * S_ + m) * D_ + n;
            d0[0]            = acc[mt][nt][0] + b0v;
            d0[1]            = acc[mt][nt][1] + b1v;
            d0[8 * D_]       = acc[mt][nt][2] + b0v;
            d0[8 * D_ + 1]   = acc[mt][nt][3] + b1v;
        }
    }
}

// ---------------- K4: fused attention (R9/R12 config: 64-row q-tiles, streamed K/V) --------
#define ATTN_SMEM_BYTES (28672 * 4)

__global__ __launch_bounds__(256, 2) void fused_attn_kernel(const int* __restrict__ mask) {
    extern __shared__ float smf[];
    float* Qt = smf;
    float* Ps = smf + 12288;

    int z = blockIdx.x;
    int bh = z >> 2, qt = z & 3;
    int b = bh >> 3, h = bh & 7;
    int tid = threadIdx.x;
    int warp = tid >> 5, lane = tid & 31;

    const float* ksrc = g_kh + (size_t)bh * 16384;   // [dk][256]
    const float* vsrc = g_vh + (size_t)bh * 16384;   // [256][64]
    const float* qsrc = g_qh + (size_t)bh * 16384 + qt * 64;

    // load Qt[dk][0..63]
    {
#pragma unroll
        for (int j = 0; j < 4; j++) {
            int lin = tid + j * 256;
            int dk = lin >> 4, c = (lin & 15) * 4;
            *(float4*)&Qt[dk * 64 + c] = *(const float4*)(qsrc + (size_t)dk * S_ + c);
        }
    }

    // preload K chunk 0 into Buf0
    {
        float* dst = smf + 4096;
#pragma unroll
        for (int j = 0; j < 4; j++) {
            int lin = tid + j * 256;
            int dk = lin >> 4, c = (lin & 15) * 4;
            *(float4*)&dst[dk * 64 + c] = *(const float4*)(ksrc + (size_t)dk * S_ + c);
        }
    }
    __syncthreads();

    // -------- GEMM1: scores over 4 K-chunks --------
    float pf[8][8];
    for (int ch = 0; ch < 4; ch++) {
        float4 nx[4];
        if (ch < 3) {
#pragma unroll
            for (int j = 0; j < 4; j++) {
                int lin = tid + j * 256;
                int dk = lin >> 4, c = (lin & 15) * 4;
                nx[j] = *(const float4*)(ksrc + (size_t)dk * S_ + (ch + 1) * 64 + c);
            }
        }
        const float* cur = smf + 4096 + (ch & 1) * 4096;

        uint64_t pch[8] = {};
        {
            float4 x0 = *(const float4*)&Qt[warp * 8];
            float4 x1 = *(const float4*)&Qt[warp * 8 + 4];
            uint64_t kk = *(const uint64_t*)&cur[lane * 2];
#pragma unroll 8
            for (int dk = 0; dk < 64; dk++) {
                float a[8] = {x0.x, x0.y, x0.z, x0.w, x1.x, x1.y, x1.z, x1.w};
                uint64_t kc = kk;
                if (dk < 63) {
                    x0 = *(const float4*)&Qt[(dk + 1) * 64 + warp * 8];
                    x1 = *(const float4*)&Qt[(dk + 1) * 64 + warp * 8 + 4];
                    kk = *(const uint64_t*)&cur[(dk + 1) * 64 + lane * 2];
                }
#pragma unroll
                for (int i = 0; i < 8; i++) fma2(pch[i], bcast2(a[i]), kc);
            }
        }
#pragma unroll
        for (int i = 0; i < 8; i++) {
            float2 f = unpack2(pch[i]);
            pf[i][2 * ch]     = f.x;
            pf[i][2 * ch + 1] = f.y;
        }

        if (ch < 3) {
            float* nb2 = smf + 4096 + ((ch + 1) & 1) * 4096;
#pragma unroll
            for (int j = 0; j < 4; j++) {
                int lin = tid + j * 256;
                int dk = lin >> 4, c = (lin & 15) * 4;
                *(float4*)&nb2[dk * 64 + c] = nx[j];
            }
        }
        __syncthreads();
    }

    // -------- mask + softmax --------
#pragma unroll
    for (int i = 0; i < 8; i++) {
        int r = qt * 64 + warp * 8 + i;
#pragma unroll
        for (int c = 0; c < 4; c++) {
            int2 mm = *(const int2*)&mask[r * S_ + c * 64 + lane * 2];
            pf[i][2 * c]     = (mm.x == 0) ? -1e9f : pf[i][2 * c]     * 0.125f;
            pf[i][2 * c + 1] = (mm.y == 0) ? -1e9f : pf[i][2 * c + 1] * 0.125f;
        }
        float mx = pf[i][0];
#pragma unroll
        for (int j = 1; j < 8; j++) mx = fmaxf(mx, pf[i][j]);
#pragma unroll
        for (int off = 16; off > 0; off >>= 1)
            mx = fmaxf(mx, __shfl_xor_sync(0xffffffffu, mx, off));
        float sum = 0.0f;
#pragma unroll
        for (int j = 0; j < 8; j++) { pf[i][j] = __expf(pf[i][j] - mx); sum += pf[i][j]; }
#pragma unroll
        for (int off = 16; off > 0; off >>= 1)
            sum += __shfl_xor_sync(0xffffffffu, sum, off);
        float inv = 1.0f / sum;
#pragma unroll
        for (int j = 0; j < 8; j++) pf[i][j] *= inv;
    }

    // write Ps[row][col]
#pragma unroll
    for (int i = 0; i < 8; i++) {
        int row = warp * 8 + i;
#pragma unroll
        for (int c = 0; c < 4; c++) {
            *(float2*)&Ps[row * 256 + c * 64 + lane * 2] =
                make_float2(pf[i][2 * c], pf[i][2 * c + 1]);
        }
    }

    // preload V chunk 0 into Buf0
    {
        float4* dst = (float4*)(smf + 4096);
        const float4* src = (const float4*)vsrc;
#pragma unroll
        for (int j = 0; j < 4; j++) dst[tid + j * 256] = src[tid + j * 256];
    }
    __syncthreads();

    // -------- GEMM2: ctx = Ps @ V over 4 V-chunks --------
    const int ty2 = tid >> 4, tx2 = tid & 15;
    uint64_t c2p[4][2] = {};
    for (int ch = 0; ch < 4; ch++) {
        float4 nv[4];
        if (ch < 3) {
            const float4* src = (const float4*)(vsrc + (ch + 1) * 4096);
#pragma unroll
            for (int j = 0; j < 4; j++) nv[j] = src[tid + j * 256];
        }
        const float* Vb = smf + 4096 + (ch & 1) * 4096;

        {
            float4 av[2][4];
            uint64_t bvu[2][4][2];
#pragma unroll
            for (int i = 0; i < 4; i++)
                av[0][i] = *(const float4*)&Ps[(ty2 * 4 + i) * 256 + ch * 64];
#pragma unroll
            for (int t = 0; t < 4; t++) {
                const uint64_t* vp = (const uint64_t*)&Vb[t * 64 + tx2 * 4];
                bvu[0][t][0] = vp[0]; bvu[0][t][1] = vp[1];
            }
#pragma unroll 2
            for (int kc = 0; kc < 64; kc += 4) {
                int curb = (kc >> 2) & 1, nxt = curb ^ 1;
                if (kc < 60) {
#pragma unroll
                    for (int i = 0; i < 4; i++)
                        av[nxt][i] = *(const float4*)&Ps[(ty2 * 4 + i) * 256 + ch * 64 + kc + 4];
#pragma unroll
                    for (int t = 0; t < 4; t++) {
                        const uint64_t* vp = (const uint64_t*)&Vb[(kc + 4 + t) * 64 + tx2 * 4];
                        bvu[nxt][t][0] = vp[0]; bvu[nxt][t][1] = vp[1];
                    }
                }
#pragma unroll
                for (int t = 0; t < 4; t++) {
#pragma unroll
                    for (int i = 0; i < 4; i++) {
                        uint64_t ap = bcast2(getf4(av[curb][i], t));
                        fma2(c2p[i][0], ap, bvu[curb][t][0]);
                        fma2(c2p[i][1], ap, bvu[curb][t][1]);
                    }
                }
            }
        }

        if (ch < 3) {
            float* nb2 = smf + 4096 + ((ch + 1) & 1) * 4096;
            float4* dst = (float4*)nb2;
#pragma unroll
            for (int j = 0; j < 4; j++) dst[tid + j * 256] = nv[j];
        }
        __syncthreads();
    }

    // write ctx
#pragma unroll
    for (int i = 0; i < 4; i++) {
        int s = qt * 64 + ty2 * 4 + i;
        float2 lo = unpack2(c2p[i][0]);
        float2 hi = unpack2(c2p[i][1]);
        *(float4*)&g_ctx[((size_t)b * S_ + s) * D_ + h * DK_ + tx2 * 4] =
            make_float4(lo.x, lo.y, hi.x, hi.y);
    }
}

// ---------------- launch ----------------
extern "C" void kernel_launch(void* const* d_in, const int* in_sizes, int n_in,
                              void* d_out, int out_size) {
    const float* q    = (const float*)d_in[0];
    const float* k    = (const float*)d_in[1];
    const float* v    = (const float*)d_in[2];
    const int*   mask = (const int*)  d_in[3];
    const float* wg   = (const float*)d_in[4];
    const float* wn   = (const float*)d_in[5];
    const float* wq   = (const float*)d_in[6];
    const float* bq   = (const float*)d_in[7];
    const float* wk   = (const float*)d_in[8];
    const float* bk   = (const float*)d_in[9];
    const float* wv   = (const float*)d_in[10];
    const float* bv   = (const float*)d_in[11];
    const float* wo   = (const float*)d_in[12];
    const float* bo   = (const float*)d_in[13];
    float* out = (float*)d_out;

    cudaFuncSetAttribute(fused_attn_kernel,
                         cudaFuncAttributeMaxDynamicSharedMemorySize, ATTN_SMEM_BYTES);
    cudaFuncSetAttribute(proj_mma,
                         cudaFuncAttributeMaxDynamicSharedMemorySize, MMA_SMEM_BYTES);
    cudaFuncSetAttribute(final_mma,
                         cudaFuncAttributeMaxDynamicSharedMemorySize, MMA_SMEM_BYTES);

    xsum_kernel<<<B_, 512>>>(q);
    gating_kernel<<<1, 1024>>>(wg, wn, out, out_size);
    proj_mma<<<dim3(4, 2, B_ * 3), 256, MMA_SMEM_BYTES>>>(q, k, v, wq, wk, wv, bq, bk, bv);
    fused_attn_kernel<<<B_ * H_ * 4, 256, ATTN_SMEM_BYTES>>>(mask);
    final_mma<<<dim3(4, 2, B_), 256, MMA_SMEM_BYTES>>>(wo, bo, out);
}

// round 16
// speedup vs baseline: 1.7167x; 1.3170x over previous
#include <cuda_runtime.h>
#include <cstdint>

#define E_  8
#define H_  8
#define D_  512
#define B_  16
#define S_  256
#define DK_ 64

// ---------------- scratch ----------------
__device__ float g_xsum[B_ * D_];
__device__ int   g_sel[B_];
__device__ float g_qh[B_ * H_ * S_ * DK_];          // [b][h][s][dk]   (NEW: row-major)
__device__ float g_kh[B_ * H_ * DK_ * S_];          // [b][h][dk][s]
__device__ float g_vh[B_ * H_ * S_ * DK_];          // [b][h][s][dk]
__device__ float g_ctx[B_ * S_ * D_];

// ---------------- helpers ----------------
__device__ __forceinline__ uint32_t f2h2(float lo, float hi) {
    uint32_t r;
    asm("cvt.rn.f16x2.f32 %0, %1, %2;" : "=r"(r) : "f"(hi), "f"(lo));
    return r;
}

__device__ __forceinline__ void mma_f16(float* c, const uint32_t* a, const uint32_t* b) {
    asm volatile(
        "mma.sync.aligned.m16n8k16.row.col.f32.f16.f16.f32 "
        "{%0,%1,%2,%3}, {%4,%5,%6,%7}, {%8,%9}, {%0,%1,%2,%3};"
        : "+f"(c[0]), "+f"(c[1]), "+f"(c[2]), "+f"(c[3])
        : "r"(a[0]), "r"(a[1]), "r"(a[2]), "r"(a[3]), "r"(b[0]), "r"(b[1]));
}

__device__ __forceinline__ float getf4(float4 v, int t) {
    switch (t) {
        case 0: return v.x;
        case 1: return v.y;
        case 2: return v.z;
        default: return v.w;
    }
}

// ---------------- threefry2x32 (JAX partitionable, key=(0,42)) ----------------
__device__ __forceinline__ uint32_t rotl32(uint32_t x, int r) {
    return (x << r) | (x >> (32 - r));
}
__device__ void threefry2x32(uint32_t k0, uint32_t k1, uint32_t c0, uint32_t c1,
                             uint32_t* o0, uint32_t* o1) {
    uint32_t ks2 = k0 ^ k1 ^ 0x1BD11BDAu;
    uint32_t x0 = c0 + k0;
    uint32_t x1 = c1 + k1;
    const int R0[4] = {13, 15, 26, 6};
    const int R1[4] = {17, 29, 16, 24};
#pragma unroll
    for (int i = 0; i < 4; i++) { x0 += x1; x1 = rotl32(x1, R0[i]); x1 ^= x0; }
    x0 += k1;  x1 += ks2 + 1u;
#pragma unroll
    for (int i = 0; i < 4; i++) { x0 += x1; x1 = rotl32(x1, R1[i]); x1 ^= x0; }
    x0 += ks2; x1 += k0 + 2u;
#pragma unroll
    for (int i = 0; i < 4; i++) { x0 += x1; x1 = rotl32(x1, R0[i]); x1 ^= x0; }
    x0 += k0;  x1 += k1 + 3u;
#pragma unroll
    for (int i = 0; i < 4; i++) { x0 += x1; x1 = rotl32(x1, R1[i]); x1 ^= x0; }
    x0 += k1;  x1 += ks2 + 4u;
#pragma unroll
    for (int i = 0; i < 4; i++) { x0 += x1; x1 = rotl32(x1, R0[i]); x1 ^= x0; }
    x0 += ks2; x1 += k0 + 5u;
    *o0 = x0; *o1 = x1;
}

__device__ float erfinv_xla(float x) {
    float w = -log1pf(-x * x);
    float p;
    if (w < 5.0f) {
        w -= 2.5f;
        p = 2.81022636e-08f;
        p = fmaf(p, w, 3.43273939e-07f);
        p = fmaf(p, w, -3.5233877e-06f);
        p = fmaf(p, w, -4.39150654e-06f);
        p = fmaf(p, w, 0.00021858087f);
        p = fmaf(p, w, -0.00125372503f);
        p = fmaf(p, w, -0.00417768164f);
        p = fmaf(p, w, 0.246640727f);
        p = fmaf(p, w, 1.50140941f);
    } else {
        w = sqrtf(w) - 3.0f;
        p = -0.000200214257f;
        p = fmaf(p, w, 0.000100950558f);
        p = fmaf(p, w, 0.00134934322f);
        p = fmaf(p, w, -0.00367342844f);
        p = fmaf(p, w, 0.00573950773f);
        p = fmaf(p, w, -0.0076224613f);
        p = fmaf(p, w, 0.00943887047f);
        p = fmaf(p, w, 1.00167406f);
        p = fmaf(p, w, 2.83297682f);
    }
    return p * x;
}

// ---------------- K1: full xsum ----------------
__global__ void xsum_kernel(const float* __restrict__ q) {
    int b = blockIdx.x, d = threadIdx.x;
    const float* p = q + (size_t)b * S_ * D_ + d;
    float acc = 0.0f;
#pragma unroll 16
    for (int s = 0; s < S_; s++) acc += p[s * D_];
    g_xsum[b * D_ + d] = acc;
}

// ---------------- K2: gating ----------------
__global__ __launch_bounds__(1024) void gating_kernel(const float* __restrict__ wg,
                                                      const float* __restrict__ wn,
                                                      float* __restrict__ d_out,
                                                      int out_size) {
    int tid = threadIdx.x;
    int be = tid & 127, slice = tid >> 7;
    int b = be >> 3, e = be & 7;

    float clp = 0.0f, rnp = 0.0f;
#pragma unroll 8
    for (int i = slice * 64; i < slice * 64 + 64; i++) {
        float xs = g_xsum[b * D_ + i];
        clp = fmaf(xs, wg[i * E_ + e], clp);
        rnp = fmaf(xs, wn[i * E_ + e], rnp);
    }

    __shared__ float scl[8][128], srn[8][128];
    __shared__ float s_noisy[128], s_thrin[B_], s_throut[B_];
    __shared__ float s_load[E_], s_imp[E_];
    scl[slice][be] = clp; srn[slice][be] = rnp;
    if (tid < E_) { s_load[tid] = 0.0f; s_imp[tid] = 0.0f; }
    __syncthreads();

    float cl = 0.0f, rn = 0.0f, stdv = 1.0f, noisy = 0.0f;
    if (tid < 128) {
#pragma unroll
        for (int s = 0; s < 8; s++) { cl += scl[s][tid]; rn += srn[s][tid]; }

        float sp = fmaxf(rn, 0.0f) + log1pf(expf(-fabsf(rn)));
        stdv = sp + 0.01f;

        uint32_t o0, o1;
        threefry2x32(0u, 42u, 0u, (uint32_t)tid, &o0, &o1);
        uint32_t bits = o0 ^ o1;
        uint32_t fb = (bits >> 9) | 0x3f800000u;
        float f = __uint_as_float(fb) - 1.0f;
        float u = f * 2.0f + (-0.99999994f);
        u = fmaxf(-0.99999994f, u);
        float z = 1.41421354f * erfinv_xla(u);
        noisy = cl + z * stdv;
        s_noisy[tid] = noisy;
    }
    __syncthreads();

    if (tid < B_) {
        float m1 = -3.0e38f, m2 = -3.0e38f;
        int i1 = 0;
        for (int ee = 0; ee < E_; ee++) {
            float val = s_noisy[tid * 8 + ee];
            if (val > m1) { m2 = m1; m1 = val; i1 = ee; }
            else if (val > m2) { m2 = val; }
        }
        g_sel[tid] = i1;
        s_thrin[tid] = m2;
        s_throut[tid] = m1;
        atomicAdd(&s_imp[i1], 1.0f);
    }
    __syncthreads();

    if (tid < 128) {
        float thr = (noisy > s_thrin[b]) ? s_thrin[b] : s_throut[b];
        float arg = ((cl - thr) / stdv) / 1.41421354f;
        float ph = 0.5f * (1.0f + erff(arg));
        atomicAdd(&s_load[e], ph);
    }
    __syncthreads();

    if (tid == 0) {
        auto cv2 = [](const float* x) {
            float mean = 0.0f;
            for (int i = 0; i < E_; i++) mean += x[i];
            mean *= (1.0f / E_);
            float var = 0.0f;
            for (int i = 0; i < E_; i++) { float d = x[i] - mean; var += d * d; }
            var *= (1.0f / (E_ - 1));
            return var / (mean * mean + 1e-10f);
        };
        float loss = 0.01f * (cv2(s_imp) + cv2(s_load));
        if (out_size > B_ * S_ * D_) d_out[B_ * S_ * D_] = loss;
    }
}

// ---------------- fp16 mma.sync mainloop (128x128 block, K=512) — R15, unchanged ----------
#define SAH_ 20
#define SBH_ 136
#define MMA_SMEM_BYTES ((2560 + 2176) * 4)

__device__ __forceinline__ void mma_mainloop(
        uint32_t* sm, const float* __restrict__ A, int lda,
        const float* __restrict__ W, int n0, float acc[4][4][4]) {
    const int tid = threadIdx.x;
    const int wid = tid >> 5, lane = tid & 31;
    const int wm = (wid & 1) * 64, wn = (wid >> 1) * 32;
    const int group = lane >> 2, tig = lane & 3;

    const int arow = tid >> 1, acw = (tid & 1) * 8;
    const int kp = tid >> 4, nb = (tid & 15) * 8;

    uint32_t* da = sm + arow * SAH_ + acw;
    uint32_t* smB = sm + 2560;
    const uint32_t* As = sm;
    const uint32_t* Bs = smB;

    float4 ar[4];
    float4 b0a, b0b, b1a, b1b;
#pragma unroll
    for (int i = 0; i < 4; i++)
        ar[i] = *(const float4*)(A + (size_t)arow * lda + acw * 2 + 4 * i);
    {
        const float* Wr0 = W + (size_t)(2 * kp) * D_ + n0 + nb;
        const float* Wr1 = Wr0 + D_;
        b0a = *(const float4*)(Wr0);     b0b = *(const float4*)(Wr0 + 4);
        b1a = *(const float4*)(Wr1);     b1b = *(const float4*)(Wr1 + 4);
    }
#pragma unroll
    for (int i = 0; i < 4; i++) {
        da[2*i]   = f2h2(getf4(ar[i], 0), getf4(ar[i], 1));
        da[2*i+1] = f2h2(getf4(ar[i], 2), getf4(ar[i], 3));
    }
    {
        uint32_t* dbb = smB + kp * SBH_ + nb;
#pragma unroll
        for (int j = 0; j < 4; j++) dbb[j]     = f2h2(getf4(b0a, j), getf4(b1a, j));
#pragma unroll
        for (int j = 0; j < 4; j++) dbb[4 + j] = f2h2(getf4(b0b, j), getf4(b1b, j));
    }
    __syncthreads();

    for (int t = 0; t < 16; t++) {
        if (t < 15) {
            int kb = (t + 1) * 32;
#pragma unroll
            for (int i = 0; i < 4; i++)
                ar[i] = *(const float4*)(A + (size_t)arow * lda + kb + acw * 2 + 4 * i);
            const float* Wr0 = W + (size_t)(kb + 2 * kp) * D_ + n0 + nb;
            const float* Wr1 = Wr0 + D_;
            b0a = *(const float4*)(Wr0);     b0b = *(const float4*)(Wr0 + 4);
            b1a = *(const float4*)(Wr1);     b1b = *(const float4*)(Wr1 + 4);
        }
#pragma unroll
        for (int ks = 0; ks < 2; ks++) {
            uint32_t af[4][4], bf[4][2];
#pragma unroll
            for (int mt = 0; mt < 4; mt++) {
                int r0 = wm + mt * 16 + group;
                af[mt][0] = As[r0 * SAH_ + ks * 8 + tig];
                af[mt][1] = As[(r0 + 8) * SAH_ + ks * 8 + tig];
                af[mt][2] = As[r0 * SAH_ + ks * 8 + tig + 4];
                af[mt][3] = As[(r0 + 8) * SAH_ + ks * 8 + tig + 4];
            }
#pragma unroll
            for (int nt = 0; nt < 4; nt++) {
                int c0 = wn + nt * 8 + group;
                bf[nt][0] = Bs[(ks * 8 + tig) * SBH_ + c0];
                bf[nt][1] = Bs[(ks * 8 + tig + 4) * SBH_ + c0];
            }
#pragma unroll
            for (int mt = 0; mt < 4; mt++)
#pragma unroll
                for (int nt = 0; nt < 4; nt++)
                    mma_f16(acc[mt][nt], af[mt], bf[nt]);
        }
        if (t < 15) {
            __syncthreads();
#pragma unroll
            for (int i = 0; i < 4; i++) {
                da[2*i]   = f2h2(getf4(ar[i], 0), getf4(ar[i], 1));
                da[2*i+1] = f2h2(getf4(ar[i], 2), getf4(ar[i], 3));
            }
            uint32_t* dbb = smB + kp * SBH_ + nb;
#pragma unroll
            for (int j = 0; j < 4; j++) dbb[j]     = f2h2(getf4(b0a, j), getf4(b1a, j));
#pragma unroll
            for (int j = 0; j < 4; j++) dbb[4 + j] = f2h2(getf4(b0b, j), getf4(b1b, j));
            __syncthreads();
        }
    }
}

// ---------------- K3: projections (q,v -> [s][dk]; k -> [dk][s]) ----------------
__global__ __launch_bounds__(256, 2) void proj_mma(
        const float* __restrict__ q, const float* __restrict__ k,
        const float* __restrict__ v,
        const float* __restrict__ wq, const float* __restrict__ wk,
        const float* __restrict__ wv,
        const float* __restrict__ bq, const float* __restrict__ bk,
        const float* __restrict__ bv) {
    extern __shared__ uint32_t smu[];
    int z = blockIdx.z;
    int b = z / 3, p = z % 3;
    int e = g_sel[b];
    const float* X = (p == 0 ? q : (p == 1 ? k : v)) + (size_t)b * S_ * D_;
    const float* W = (p == 0 ? wq : (p == 1 ? wk : wv)) + (size_t)e * D_ * D_;
    const float* bias = (p == 0 ? bq : (p == 1 ? bk : bv)) + e * D_;
    float* Out = (p == 0 ? g_qh : (p == 1 ? g_kh : g_vh));
    int bn = blockIdx.x * 128, m0 = blockIdx.y * 128;

    float acc[4][4][4] = {};
    mma_mainloop(smu, X + (size_t)m0 * D_, D_, W, bn, acc);

    const int lane = threadIdx.x & 31, wid = threadIdx.x >> 5;
    const int wm = (wid & 1) * 64, wn = (wid >> 1) * 32;
    const int group = lane >> 2, tig = lane & 3;

#pragma unroll
    for (int mt = 0; mt < 4; mt++) {
#pragma unroll
        for (int nt = 0; nt < 4; nt++) {
            int n = bn + wn + nt * 8 + 2 * tig;
            int m = m0 + wm + mt * 16 + group;
            int h = n >> 6, dk = n & 63;
            float b0v = bias[n], b1v = bias[n + 1];
            if (p == 1) {
                size_t base = ((size_t)(b * H_ + h) * DK_ + dk) * S_;
                Out[base + m]            = acc[mt][nt][0] + b0v;
                Out[base + S_ + m]       = acc[mt][nt][1] + b1v;
                Out[base + m + 8]        = acc[mt][nt][2] + b0v;
                Out[base + S_ + m + 8]   = acc[mt][nt][3] + b1v;
            } else {
                size_t base = ((size_t)(b * H_ + h) * S_ + m) * DK_ + dk;
                Out[base]                = acc[mt][nt][0] + b0v;
                Out[base + 1]            = acc[mt][nt][1] + b1v;
                Out[base + 8 * DK_]      = acc[mt][nt][2] + b0v;
                Out[base + 8 * DK_ + 1]  = acc[mt][nt][3] + b1v;
            }
        }
    }
}

// ---------------- K5: final projection ----------------
__global__ __launch_bounds__(256, 2) void final_mma(const float* __restrict__ wo,
                                                    const float* __restrict__ bo,
                                                    float* __restrict__ out) {
    extern __shared__ uint32_t smu[];
    int b = blockIdx.z;
    int e = g_sel[b];
    const float* A = g_ctx + (size_t)b * S_ * D_;
    const float* W = wo + (size_t)e * D_ * D_;
    const float* bias = bo + e * D_;
    int bn = blockIdx.x * 128, m0 = blockIdx.y * 128;

    float acc[4][4][4] = {};
    mma_mainloop(smu, A + (size_t)m0 * D_, D_, W, bn, acc);

    const int lane = threadIdx.x & 31, wid = threadIdx.x >> 5;
    const int wm = (wid & 1) * 64, wn = (wid >> 1) * 32;
    const int group = lane >> 2, tig = lane & 3;

#pragma unroll
    for (int mt = 0; mt < 4; mt++) {
#pragma unroll
        for (int nt = 0; nt < 4; nt++) {
            int n = bn + wn + nt * 8 + 2 * tig;
            int m = m0 + wm + mt * 16 + group;
            float b0v = bias[n], b1v = bias[n + 1];
            float* d0 = out + ((size_t)b * S_ + m) * D_ + n;
            d0[0]            = acc[mt][nt][0] + b0v;
            d0[1]            = acc[mt][nt][1] + b1v;
            d0[8 * D_]       = acc[mt][nt][2] + b0v;
            d0[8 * D_ + 1]   = acc[mt][nt][3] + b1v;
        }
    }
}

// ---------------- K4: fused attention via fp16 mma ----------------
// block = (b, h, 64-row q tile); 8 warps: warp = (mt = w>>1, half = w&1)
// smem words: Qa @0 (64x36=2304) | Kb @2304 (32x264=8448) | Vb @10752 (128x72=9216)
//             smax/ssum @19968 (128+128 floats)   total 20224 words = 80896 B
// ctxred (4x16x65 floats = 4160) overlays Kb (safe: Kb dead after first softmax sync)
#define ATTN_SMEM_BYTES (20224 * 4)

__global__ __launch_bounds__(256, 2) void fused_attn_kernel(const int* __restrict__ mask) {
    extern __shared__ uint32_t smw[];
    uint32_t* Qa = smw;
    uint32_t* Kb = smw + 2304;
    uint32_t* Vb = smw + 10752;
    float* smax = (float*)(smw + 19968);       // [64 rows][2 halves]
    float* ssum = smax + 128;
    float* ctxred = (float*)(smw + 2304);      // [4 mt][16 rows][65]

    int z = blockIdx.x;
    int bh = z >> 2, qt = z & 3;
    int b = bh >> 3, h = bh & 7;
    int tid = threadIdx.x, wid = tid >> 5, lane = tid & 31;
    int mt = wid >> 1, half = wid & 1;
    int group = lane >> 2, tig = lane & 3;

    const float* qsrc = g_qh + (size_t)bh * 16384 + (size_t)qt * 64 * DK_;  // [s][dk]
    const float* ksrc = g_kh + (size_t)bh * 16384;                          // [dk][s]
    const float* vsrc = g_vh + (size_t)bh * 16384;                          // [s][dk]

    // ---- stage Q [64 m][32 kw], stride 36
    {
        int m = tid >> 2, c = (tid & 3) * 16;
#pragma unroll
        for (int i = 0; i < 2; i++) {
            float4 v0 = *(const float4*)(qsrc + (size_t)m * DK_ + c + 8 * i);
            float4 v1 = *(const float4*)(qsrc + (size_t)m * DK_ + c + 8 * i + 4);
            uint2 w2a = make_uint2(f2h2(v0.x, v0.y), f2h2(v0.z, v0.w));
            uint2 w2b = make_uint2(f2h2(v1.x, v1.y), f2h2(v1.z, v1.w));
            *(uint2*)&Qa[m * 36 + (c >> 1) + 4 * i]     = w2a;
            *(uint2*)&Qa[m * 36 + (c >> 1) + 4 * i + 2] = w2b;
        }
    }
    // ---- stage K [32 kp][256 n], stride 264
#pragma unroll
    for (int j = 0; j < 8; j++) {
        int lin = tid + 256 * j;
        int kp = lin >> 6, nq = (lin & 63) * 4;
        float4 r0 = *(const float4*)(ksrc + (size_t)(2 * kp) * S_ + nq);
        float4 r1 = *(const float4*)(ksrc + (size_t)(2 * kp + 1) * S_ + nq);
        uint4 w4 = make_uint4(f2h2(r0.x, r1.x), f2h2(r0.y, r1.y),
                              f2h2(r0.z, r1.z), f2h2(r0.w, r1.w));
        *(uint4*)&Kb[kp * 264 + nq] = w4;
    }
    // ---- stage V^T [128 kp_s][64 n_dk], stride 72
#pragma unroll
    for (int j = 0; j < 8; j++) {
        int lin = tid + 256 * j;
        int kp = lin >> 4, nq = (lin & 15) * 4;
        float4 r0 = *(const float4*)(vsrc + (size_t)(2 * kp) * DK_ + nq);
        float4 r1 = *(const float4*)(vsrc + (size_t)(2 * kp + 1) * DK_ + nq);
        uint4 w4 = make_uint4(f2h2(r0.x, r1.x), f2h2(r0.y, r1.y),
                              f2h2(r0.z, r1.z), f2h2(r0.w, r1.w));
        *(uint4*)&Vb[kp * 72 + nq] = w4;
    }
    __syncthreads();

    // ---- GEMM1: scores[mt rows16][half cols128] in fragments sc[16][4]
    float sc[16][4] = {};
    const int m0 = mt * 16;
#pragma unroll
    for (int ks = 0; ks < 4; ks++) {
        uint32_t af[4];
        af[0] = Qa[(m0 + group) * 36 + ks * 8 + tig];
        af[1] = Qa[(m0 + group + 8) * 36 + ks * 8 + tig];
        af[2] = Qa[(m0 + group) * 36 + ks * 8 + tig + 4];
        af[3] = Qa[(m0 + group + 8) * 36 + ks * 8 + tig + 4];
#pragma unroll
        for (int nt = 0; nt < 16; nt++) {
            int n = half * 128 + nt * 8 + group;
            uint32_t bf[2];
            bf[0] = Kb[(ks * 8 + tig) * 264 + n];
            bf[1] = Kb[(ks * 8 + tig + 4) * 264 + n];
            mma_f16(sc[nt], af, bf);
        }
    }

    // ---- mask + scale
    const int rbase = qt * 64 + mt * 16;
#pragma unroll
    for (int nt = 0; nt < 16; nt++) {
        int col = half * 128 + nt * 8 + 2 * tig;
        int2 mr0 = *(const int2*)&mask[(rbase + group) * S_ + col];
        int2 mr1 = *(const int2*)&mask[(rbase + group + 8) * S_ + col];
        sc[nt][0] = mr0.x ? sc[nt][0] * 0.125f : -1e9f;
        sc[nt][1] = mr0.y ? sc[nt][1] * 0.125f : -1e9f;
        sc[nt][2] = mr1.x ? sc[nt][2] * 0.125f : -1e9f;
        sc[nt][3] = mr1.y ? sc[nt][3] * 0.125f : -1e9f;
    }

    // all warps done reading Kb before ctxred/smax traffic
    __syncthreads();

    // ---- softmax: rows r0=group, r1=group+8 of this mt tile
    float mx0 = -3.0e38f, mx1 = -3.0e38f;
#pragma unroll
    for (int nt = 0; nt < 16; nt++) {
        mx0 = fmaxf(mx0, fmaxf(sc[nt][0], sc[nt][1]));
        mx1 = fmaxf(mx1, fmaxf(sc[nt][2], sc[nt][3]));
    }
#pragma unroll
    for (int off = 1; off < 4; off <<= 1) {
        mx0 = fmaxf(mx0, __shfl_xor_sync(0xffffffffu, mx0, off));
        mx1 = fmaxf(mx1, __shfl_xor_sync(0xffffffffu, mx1, off));
    }
    if (tig == 0) {
        smax[(mt * 16 + group) * 2 + half]     = mx0;
        smax[(mt * 16 + group + 8) * 2 + half] = mx1;
    }
    __syncthreads();
    mx0 = fmaxf(smax[(mt * 16 + group) * 2],     smax[(mt * 16 + group) * 2 + 1]);
    mx1 = fmaxf(smax[(mt * 16 + group + 8) * 2], smax[(mt * 16 + group + 8) * 2 + 1]);

    float s0 = 0.0f, s1 = 0.0f;
#pragma unroll
    for (int nt = 0; nt < 16; nt++) {
        sc[nt][0] = __expf(sc[nt][0] - mx0); s0 += sc[nt][0];
        sc[nt][1] = __expf(sc[nt][1] - mx0); s0 += sc[nt][1];
        sc[nt][2] = __expf(sc[nt][2] - mx1); s1 += sc[nt][2];
        sc[nt][3] = __expf(sc[nt][3] - mx1); s1 += sc[nt][3];
    }
#pragma unroll
    for (int off = 1; off < 4; off <<= 1) {
        s0 += __shfl_xor_sync(0xffffffffu, s0, off);
        s1 += __shfl_xor_sync(0xffffffffu, s1, off);
    }
    if (tig == 0) {
        ssum[(mt * 16 + group) * 2 + half]     = s0;
        ssum[(mt * 16 + group + 8) * 2 + half] = s1;
    }
    __syncthreads();
    float inv0 = 1.0f / (ssum[(mt * 16 + group) * 2] + ssum[(mt * 16 + group) * 2 + 1]);
    float inv1 = 1.0f / (ssum[(mt * 16 + group + 8) * 2] + ssum[(mt * 16 + group + 8) * 2 + 1]);
#pragma unroll
    for (int nt = 0; nt < 16; nt++) {
        sc[nt][0] *= inv0; sc[nt][1] *= inv0;
        sc[nt][2] *= inv1; sc[nt][3] *= inv1;
    }

    // ---- GEMM2: ctx partial over k = half*128..+127; A = P fragments (register repack)
    float ca[8][4] = {};
#pragma unroll
    for (int ks2 = 0; ks2 < 8; ks2++) {
        uint32_t af[4];
        af[0] = f2h2(sc[2 * ks2][0],     sc[2 * ks2][1]);
        af[1] = f2h2(sc[2 * ks2][2],     sc[2 * ks2][3]);
        af[2] = f2h2(sc[2 * ks2 + 1][0], sc[2 * ks2 + 1][1]);
        af[3] = f2h2(sc[2 * ks2 + 1][2], sc[2 * ks2 + 1][3]);
        int kpb = half * 64 + ks2 * 8;
#pragma unroll
        for (int nt2 = 0; nt2 < 8; nt2++) {
            uint32_t bf[2];
            bf[0] = Vb[(kpb + tig) * 72 + nt2 * 8 + group];
            bf[1] = Vb[(kpb + tig + 4) * 72 + nt2 * 8 + group];
            mma_f16(ca[nt2], af, bf);
        }
    }

    // ---- cross-half reduce + write
    float* cr = ctxred + mt * 16 * 65;
    if (half == 0) {
#pragma unroll
        for (int nt2 = 0; nt2 < 8; nt2++) {
            int c0 = nt2 * 8 + 2 * tig;
            cr[group * 65 + c0]           = ca[nt2][0];
            cr[group * 65 + c0 + 1]       = ca[nt2][1];
            cr[(group + 8) * 65 + c0]     = ca[nt2][2];
            cr[(group + 8) * 65 + c0 + 1] = ca[nt2][3];
        }
    }
    __syncthreads();
    if (half == 1) {
#pragma unroll
        for (int nt2 = 0; nt2 < 8; nt2++) {
            int c0 = nt2 * 8 + 2 * tig;
            float v0 = ca[nt2][0] + cr[group * 65 + c0];
            float v1 = ca[nt2][1] + cr[group * 65 + c0 + 1];
            float v2 = ca[nt2][2] + cr[(group + 8) * 65 + c0];
            float v3 = ca[nt2][3] + cr[(group + 8) * 65 + c0 + 1];
            *(float2*)&g_ctx[((size_t)b * S_ + rbase + group) * D_ + h * DK_ + c0] =
                make_float2(v0, v1);
            *(float2*)&g_ctx[((size_t)b * S_ + rbase + group + 8) * D_ + h * DK_ + c0] =
                make_float2(v2, v3);
        }
    }
}

// ---------------- launch ----------------
extern "C" void kernel_launch(void* const* d_in, const int* in_sizes, int n_in,
                              void* d_out, int out_size) {
    const float* q    = (const float*)d_in[0];
    const float* k    = (const float*)d_in[1];
    const float* v    = (const float*)d_in[2];
    const int*   mask = (const int*)  d_in[3];
    const float* wg   = (const float*)d_in[4];
    const float* wn   = (const float*)d_in[5];
    const float* wq   = (const float*)d_in[6];
    const float* bq   = (const float*)d_in[7];
    const float* wk   = (const float*)d_in[8];
    const float* bk   = (const float*)d_in[9];
    const float* wv   = (const float*)d_in[10];
    const float* bv   = (const float*)d_in[11];
    const float* wo   = (const float*)d_in[12];
    const float* bo   = (const float*)d_in[13];
    float* out = (float*)d_out;

    cudaFuncSetAttribute(fused_attn_kernel,
                         cudaFuncAttributeMaxDynamicSharedMemorySize, ATTN_SMEM_BYTES);
    cudaFuncSetAttribute(proj_mma,
                         cudaFuncAttributeMaxDynamicSharedMemorySize, MMA_SMEM_BYTES);
    cudaFuncSetAttribute(final_mma,
                         cudaFuncAttributeMaxDynamicSharedMemorySize, MMA_SMEM_BYTES);

    xsum_kernel<<<B_, 512>>>(q);
    gating_kernel<<<1, 1024>>>(wg, wn, out, out_size);
    proj_mma<<<dim3(4, 2, B_ * 3), 256, MMA_SMEM_BYTES>>>(q, k, v, wq, wk, wv, bq, bk, bv);
    fused_attn_kernel<<<B_ * H_ * 4, 256, ATTN_SMEM_BYTES>>>(mask);
    final_mma<<<dim3(4, 2, B_), 256, MMA_SMEM_BYTES>>>(wo, bo, out);
}

// round 17
// speedup vs baseline: 1.9247x; 1.1211x over previous
#include <cuda_runtime.h>
#include <cstdint>

#define E_  8
#define H_  8
#define D_  512
#define B_  16
#define S_  256
#define DK_ 64

// ---------------- scratch ----------------
__device__ float    g_xsum[B_ * D_];
__device__ int      g_sel[B_];
__device__ uint32_t g_qh_h[B_ * H_ * S_ * 32];      // [b][h][s][dk/2]  fp16x2
__device__ uint32_t g_kh_h[B_ * H_ * 32 * S_];      // [b][h][dk/2][s]  fp16x2
__device__ float    g_vh[B_ * H_ * S_ * DK_];       // [b][h][s][dk]    fp32
__device__ uint32_t g_ctx_h[B_ * S_ * (D_ / 2)];    // [b][s][D/2]      fp16x2

// ---------------- helpers ----------------
__device__ __forceinline__ uint32_t f2h2(float lo, float hi) {
    uint32_t r;
    asm("cvt.rn.f16x2.f32 %0, %1, %2;" : "=r"(r) : "f"(hi), "f"(lo));
    return r;
}

__device__ __forceinline__ void mma_f16(float* c, const uint32_t* a, const uint32_t* b) {
    asm volatile(
        "mma.sync.aligned.m16n8k16.row.col.f32.f16.f16.f32 "
        "{%0,%1,%2,%3}, {%4,%5,%6,%7}, {%8,%9}, {%0,%1,%2,%3};"
        : "+f"(c[0]), "+f"(c[1]), "+f"(c[2]), "+f"(c[3])
        : "r"(a[0]), "r"(a[1]), "r"(a[2]), "r"(a[3]), "r"(b[0]), "r"(b[1]));
}

// ---------------- threefry2x32 (JAX partitionable, key=(0,42)) ----------------
__device__ __forceinline__ uint32_t rotl32(uint32_t x, int r) {
    return (x << r) | (x >> (32 - r));
}
__device__ void threefry2x32(uint32_t k0, uint32_t k1, uint32_t c0, uint32_t c1,
                             uint32_t* o0, uint32_t* o1) {
    uint32_t ks2 = k0 ^ k1 ^ 0x1BD11BDAu;
    uint32_t x0 = c0 + k0;
    uint32_t x1 = c1 + k1;
    const int R0[4] = {13, 15, 26, 6};
    const int R1[4] = {17, 29, 16, 24};
#pragma unroll
    for (int i = 0; i < 4; i++) { x0 += x1; x1 = rotl32(x1, R0[i]); x1 ^= x0; }
    x0 += k1;  x1 += ks2 + 1u;
#pragma unroll
    for (int i = 0; i < 4; i++) { x0 += x1; x1 = rotl32(x1, R1[i]); x1 ^= x0; }
    x0 += ks2; x1 += k0 + 2u;
#pragma unroll
    for (int i = 0; i < 4; i++) { x0 += x1; x1 = rotl32(x1, R0[i]); x1 ^= x0; }
    x0 += k0;  x1 += k1 + 3u;
#pragma unroll
    for (int i = 0; i < 4; i++) { x0 += x1; x1 = rotl32(x1, R1[i]); x1 ^= x0; }
    x0 += k1;  x1 += ks2 + 4u;
#pragma unroll
    for (int i = 0; i < 4; i++) { x0 += x1; x1 = rotl32(x1, R0[i]); x1 ^= x0; }
    x0 += ks2; x1 += k0 + 5u;
    *o0 = x0; *o1 = x1;
}

__device__ float erfinv_xla(float x) {
    float w = -log1pf(-x * x);
    float p;
    if (w < 5.0f) {
        w -= 2.5f;
        p = 2.81022636e-08f;
        p = fmaf(p, w, 3.43273939e-07f);
        p = fmaf(p, w, -3.5233877e-06f);
        p = fmaf(p, w, -4.39150654e-06f);
        p = fmaf(p, w, 0.00021858087f);
        p = fmaf(p, w, -0.00125372503f);
        p = fmaf(p, w, -0.00417768164f);
        p = fmaf(p, w, 0.246640727f);
        p = fmaf(p, w, 1.50140941f);
    } else {
        w = sqrtf(w) - 3.0f;
        p = -0.000200214257f;
        p = fmaf(p, w, 0.000100950558f);
        p = fmaf(p, w, 0.00134934322f);
        p = fmaf(p, w, -0.00367342844f);
        p = fmaf(p, w, 0.00573950773f);
        p = fmaf(p, w, -0.0076224613f);
        p = fmaf(p, w, 0.00943887047f);
        p = fmaf(p, w, 1.00167406f);
        p = fmaf(p, w, 2.83297682f);
    }
    return p * x;
}

// ---------------- K1: full xsum ----------------
__global__ void xsum_kernel(const float* __restrict__ q) {
    int b = blockIdx.x, d = threadIdx.x;
    const float* p = q + (size_t)b * S_ * D_ + d;
    float acc = 0.0f;
#pragma unroll 16
    for (int s = 0; s < S_; s++) acc += p[s * D_];
    g_xsum[b * D_ + d] = acc;
}

// ---------------- K2: gating ----------------
__global__ __launch_bounds__(1024) void gating_kernel(const float* __restrict__ wg,
                                                      const float* __restrict__ wn,
                                                      float* __restrict__ d_out,
                                                      int out_size) {
    int tid = threadIdx.x;
    int be = tid & 127, slice = tid >> 7;
    int b = be >> 3, e = be & 7;

    float clp = 0.0f, rnp = 0.0f;
#pragma unroll 8
    for (int i = slice * 64; i < slice * 64 + 64; i++) {
        float xs = g_xsum[b * D_ + i];
        clp = fmaf(xs, wg[i * E_ + e], clp);
        rnp = fmaf(xs, wn[i * E_ + e], rnp);
    }

    __shared__ float scl[8][128], srn[8][128];
    __shared__ float s_noisy[128], s_thrin[B_], s_throut[B_];
    __shared__ float s_load[E_], s_imp[E_];
    scl[slice][be] = clp; srn[slice][be] = rnp;
    if (tid < E_) { s_load[tid] = 0.0f; s_imp[tid] = 0.0f; }
    __syncthreads();

    float cl = 0.0f, rn = 0.0f, stdv = 1.0f, noisy = 0.0f;
    if (tid < 128) {
#pragma unroll
        for (int s = 0; s < 8; s++) { cl += scl[s][tid]; rn += srn[s][tid]; }

        float sp = fmaxf(rn, 0.0f) + log1pf(expf(-fabsf(rn)));
        stdv = sp + 0.01f;

        uint32_t o0, o1;
        threefry2x32(0u, 42u, 0u, (uint32_t)tid, &o0, &o1);
        uint32_t bits = o0 ^ o1;
        uint32_t fb = (bits >> 9) | 0x3f800000u;
        float f = __uint_as_float(fb) - 1.0f;
        float u = f * 2.0f + (-0.99999994f);
        u = fmaxf(-0.99999994f, u);
        float z = 1.41421354f * erfinv_xla(u);
        noisy = cl + z * stdv;
        s_noisy[tid] = noisy;
    }
    __syncthreads();

    if (tid < B_) {
        float m1 = -3.0e38f, m2 = -3.0e38f;
        int i1 = 0;
        for (int ee = 0; ee < E_; ee++) {
            float val = s_noisy[tid * 8 + ee];
            if (val > m1) { m2 = m1; m1 = val; i1 = ee; }
            else if (val > m2) { m2 = val; }
        }
        g_sel[tid] = i1;
        s_thrin[tid] = m2;
        s_throut[tid] = m1;
        atomicAdd(&s_imp[i1], 1.0f);
    }
    __syncthreads();

    if (tid < 128) {
        float thr = (noisy > s_thrin[b]) ? s_thrin[b] : s_throut[b];
        float arg = ((cl - thr) / stdv) / 1.41421354f;
        float ph = 0.5f * (1.0f + erff(arg));
        atomicAdd(&s_load[e], ph);
    }
    __syncthreads();

    if (tid == 0) {
        auto cv2 = [](const float* x) {
            float mean = 0.0f;
            for (int i = 0; i < E_; i++) mean += x[i];
            mean *= (1.0f / E_);
            float var = 0.0f;
            for (int i = 0; i < E_; i++) { float d = x[i] - mean; var += d * d; }
            var *= (1.0f / (E_ - 1));
            return var / (mean * mean + 1e-10f);
        };
        float loss = 0.01f * (cv2(s_imp) + cv2(s_load));
        if (out_size > B_ * S_ * D_) d_out[B_ * S_ * D_] = loss;
    }
}

// ---------------- fp16 mma.sync mainloop, double-buffered ----------------
// smem words: A0 @0 (2560) | A1 @2560 | B0 @5120 (2176) | B1 @7296  -> 9472 w = 37888 B
#define SAH_ 20
#define SBH_ 136
#define MMA_SMEM_BYTES (9472 * 4)

template<bool AHALF>
__device__ __forceinline__ void mma_mainloop2(
        uint32_t* sm, const void* Aptr, const float* __restrict__ W, int n0,
        float acc[4][4][4]) {
    const int tid = threadIdx.x;
    const int wid = tid >> 5, lane = tid & 31;
    const int wm = (wid & 1) * 64, wn = (wid >> 1) * 32;
    const int group = lane >> 2, tig = lane & 3;

    const int arow = tid >> 1, acw = (tid & 1) * 8;   // A: row, word offset in 16-word panel row
    const int kp = tid >> 4, nb = (tid & 15) * 8;     // B: k-pair, 8 n-words per thread

    const float* Af = (const float*)Aptr;
    const uint32_t* Ah = (const uint32_t*)Aptr;

    uint4 au0, au1;
    float4 ar0, ar1, ar2, ar3;
    float4 b0a, b0b, b1a, b1b;

    // ---- prologue: load panel 0, store buf 0
    {
        if (AHALF) {
            const uint32_t* src = Ah + (size_t)arow * 256 + acw;
            au0 = *(const uint4*)(src);
            au1 = *(const uint4*)(src + 4);
        } else {
            const float* src = Af + (size_t)arow * D_ + acw * 2;
            ar0 = *(const float4*)(src);
            ar1 = *(const float4*)(src + 4);
            ar2 = *(const float4*)(src + 8);
            ar3 = *(const float4*)(src + 12);
        }
        const float* Wr0 = W + (size_t)(2 * kp) * D_ + n0 + nb;
        const float* Wr1 = Wr0 + D_;
        b0a = *(const float4*)(Wr0); b0b = *(const float4*)(Wr0 + 4);
        b1a = *(const float4*)(Wr1); b1b = *(const float4*)(Wr1 + 4);
    }
    {
        uint32_t* da = sm + arow * SAH_ + acw;
        if (AHALF) {
            *(uint4*)(da) = au0;
            *(uint4*)(da + 4) = au1;
        } else {
            *(uint4*)(da) = make_uint4(f2h2(ar0.x, ar0.y), f2h2(ar0.z, ar0.w),
                                       f2h2(ar1.x, ar1.y), f2h2(ar1.z, ar1.w));
            *(uint4*)(da + 4) = make_uint4(f2h2(ar2.x, ar2.y), f2h2(ar2.z, ar2.w),
                                           f2h2(ar3.x, ar3.y), f2h2(ar3.z, ar3.w));
        }
        uint32_t* dbb = sm + 5120 + kp * SBH_ + nb;
        *(uint4*)(dbb) = make_uint4(f2h2(b0a.x, b1a.x), f2h2(b0a.y, b1a.y),
                                    f2h2(b0a.z, b1a.z), f2h2(b0a.w, b1a.w));
        *(uint4*)(dbb + 4) = make_uint4(f2h2(b0b.x, b1b.x), f2h2(b0b.y, b1b.y),
                                        f2h2(b0b.z, b1b.z), f2h2(b0b.w, b1b.w));
    }
    __syncthreads();

    for (int t = 0; t < 16; t++) {
        int buf = t & 1;
        if (t < 15) {
            int kb = (t + 1) * 32;
            if (AHALF) {
                const uint32_t* src = Ah + (size_t)arow * 256 + (kb >> 1) + acw;
                au0 = *(const uint4*)(src);
                au1 = *(const uint4*)(src + 4);
            } else {
                const float* src = Af + (size_t)arow * D_ + kb + acw * 2;
                ar0 = *(const float4*)(src);
                ar1 = *(const float4*)(src + 4);
                ar2 = *(const float4*)(src + 8);
                ar3 = *(const float4*)(src + 12);
            }
            const float* Wr0 = W + (size_t)(kb + 2 * kp) * D_ + n0 + nb;
            const float* Wr1 = Wr0 + D_;
            b0a = *(const float4*)(Wr0); b0b = *(const float4*)(Wr0 + 4);
            b1a = *(const float4*)(Wr1); b1b = *(const float4*)(Wr1 + 4);
        }
        const uint32_t* As = sm + buf * 2560;
        const uint32_t* Bs = sm + 5120 + buf * 2176;
#pragma unroll
        for (int ks = 0; ks < 2; ks++) {
            uint32_t af[4][4], bf[4][2];
#pragma unroll
            for (int mt = 0; mt < 4; mt++) {
                int r0 = wm + mt * 16 + group;
                af[mt][0] = As[r0 * SAH_ + ks * 8 + tig];
                af[mt][1] = As[(r0 + 8) * SAH_ + ks * 8 + tig];
                af[mt][2] = As[r0 * SAH_ + ks * 8 + tig + 4];
                af[mt][3] = As[(r0 + 8) * SAH_ + ks * 8 + tig + 4];
            }
#pragma unroll
            for (int nt = 0; nt < 4; nt++) {
                int c0 = wn + nt * 8 + group;
                bf[nt][0] = Bs[(ks * 8 + tig) * SBH_ + c0];
                bf[nt][1] = Bs[(ks * 8 + tig + 4) * SBH_ + c0];
            }
#pragma unroll
            for (int mt = 0; mt < 4; mt++)
#pragma unroll
                for (int nt = 0; nt < 4; nt++)
                    mma_f16(acc[mt][nt], af[mt], bf[nt]);
        }
        if (t < 15) {
            int nbuf = buf ^ 1;
            uint32_t* da = sm + nbuf * 2560 + arow * SAH_ + acw;
            if (AHALF) {
                *(uint4*)(da) = au0;
                *(uint4*)(da + 4) = au1;
            } else {
                *(uint4*)(da) = make_uint4(f2h2(ar0.x, ar0.y), f2h2(ar0.z, ar0.w),
                                           f2h2(ar1.x, ar1.y), f2h2(ar1.z, ar1.w));
                *(uint4*)(da + 4) = make_uint4(f2h2(ar2.x, ar2.y), f2h2(ar2.z, ar2.w),
                                               f2h2(ar3.x, ar3.y), f2h2(ar3.z, ar3.w));
            }
            uint32_t* dbb = sm + 5120 + nbuf * 2176 + kp * SBH_ + nb;
            *(uint4*)(dbb) = make_uint4(f2h2(b0a.x, b1a.x), f2h2(b0a.y, b1a.y),
                                        f2h2(b0a.z, b1a.z), f2h2(b0a.w, b1a.w));
            *(uint4*)(dbb + 4) = make_uint4(f2h2(b0b.x, b1b.x), f2h2(b0b.y, b1b.y),
                                            f2h2(b0b.z, b1b.z), f2h2(b0b.w, b1b.w));
            __syncthreads();
        }
    }
}

// ---------------- K3: projections (q->[s][dk/2] h2, k->[dk/2][s] h2, v->fp32) -----------
__global__ __launch_bounds__(256, 2) void proj_mma(
        const float* __restrict__ q, const float* __restrict__ k,
        const float* __restrict__ v,
        const float* __restrict__ wq, const float* __restrict__ wk,
        const float* __restrict__ wv,
        const float* __restrict__ bq, const float* __restrict__ bk,
        const float* __restrict__ bv) {
    extern __shared__ uint32_t smu[];
    int z = blockIdx.z;
    int b = z / 3, p = z % 3;
    int e = g_sel[b];
    const float* X = (p == 0 ? q : (p == 1 ? k : v)) + (size_t)b * S_ * D_;
    const float* W = (p == 0 ? wq : (p == 1 ? wk : wv)) + (size_t)e * D_ * D_;
    const float* bias = (p == 0 ? bq : (p == 1 ? bk : bv)) + e * D_;
    int bn = blockIdx.x * 128, m0 = blockIdx.y * 128;

    float acc[4][4][4] = {};
    mma_mainloop2<false>(smu, X + (size_t)m0 * D_, W, bn, acc);

    const int lane = threadIdx.x & 31, wid = threadIdx.x >> 5;
    const int wm = (wid & 1) * 64, wn = (wid >> 1) * 32;
    const int group = lane >> 2, tig = lane & 3;

#pragma unroll
    for (int mt = 0; mt < 4; mt++) {
#pragma unroll
        for (int nt = 0; nt < 4; nt++) {
            int n = bn + wn + nt * 8 + 2 * tig;
            int m = m0 + wm + mt * 16 + group;
            int h = n >> 6, dk = n & 63;
            float b0v = bias[n], b1v = bias[n + 1];
            if (p == 0) {
                uint32_t w0 = f2h2(acc[mt][nt][0] + b0v, acc[mt][nt][1] + b1v);
                uint32_t w1 = f2h2(acc[mt][nt][2] + b0v, acc[mt][nt][3] + b1v);
                size_t base = ((size_t)(b * H_ + h) * S_ + m) * 32 + (dk >> 1);
                g_qh_h[base]          = w0;
                g_qh_h[base + 8 * 32] = w1;
            } else if (p == 1) {
                uint32_t w0 = f2h2(acc[mt][nt][0] + b0v, acc[mt][nt][1] + b1v);
                uint32_t w1 = f2h2(acc[mt][nt][2] + b0v, acc[mt][nt][3] + b1v);
                size_t base = ((size_t)(b * H_ + h) * 32 + (dk >> 1)) * S_ + m;
                g_kh_h[base]     = w0;
                g_kh_h[base + 8] = w1;
            } else {
                size_t base = ((size_t)(b * H_ + h) * S_ + m) * DK_ + dk;
                g_vh[base]                = acc[mt][nt][0] + b0v;
                g_vh[base + 1]            = acc[mt][nt][1] + b1v;
                g_vh[base + 8 * DK_]      = acc[mt][nt][2] + b0v;
                g_vh[base + 8 * DK_ + 1]  = acc[mt][nt][3] + b1v;
            }
        }
    }
}

// ---------------- K5: final projection (A = fp16 ctx) ----------------
__global__ __launch_bounds__(256, 2) void final_mma(const float* __restrict__ wo,
                                                    const float* __restrict__ bo,
                                                    float* __restrict__ out) {
    extern __shared__ uint32_t smu[];
    int b = blockIdx.z;
    int e = g_sel[b];
    const uint32_t* A = g_ctx_h + (size_t)b * S_ * 256;
    const float* W = wo + (size_t)e * D_ * D_;
    const float* bias = bo + e * D_;
    int bn = blockIdx.x * 128, m0 = blockIdx.y * 128;

    float acc[4][4][4] = {};
    mma_mainloop2<true>(smu, A + (size_t)m0 * 256, W, bn, acc);

    const int lane = threadIdx.x & 31, wid = threadIdx.x >> 5;
    const int wm = (wid & 1) * 64, wn = (wid >> 1) * 32;
    const int group = lane >> 2, tig = lane & 3;

#pragma unroll
    for (int mt = 0; mt < 4; mt++) {
#pragma unroll
        for (int nt = 0; nt < 4; nt++) {
            int n = bn + wn + nt * 8 + 2 * tig;
            int m = m0 + wm + mt * 16 + group;
            float b0v = bias[n], b1v = bias[n + 1];
            float* d0 = out + ((size_t)b * S_ + m) * D_ + n;
            d0[0]            = acc[mt][nt][0] + b0v;
            d0[1]            = acc[mt][nt][1] + b1v;
            d0[8 * D_]       = acc[mt][nt][2] + b0v;
            d0[8 * D_ + 1]   = acc[mt][nt][3] + b1v;
        }
    }
}

// ---------------- K4: fused attention via fp16 mma (fp16 inputs) ----------------
// smem words: Qa @0 (64x36=2304) | Kb @2304 (32x264=8448) | Vb @10752 (128x72=9216)
//             smax/ssum @19968 (256 floats)   total 20224 words
// ctxred (4x16x65) overlays Kb after GEMM1
#define ATTN_SMEM_BYTES (20224 * 4)

__global__ __launch_bounds__(256, 2) void fused_attn_kernel(const int* __restrict__ mask) {
    extern __shared__ uint32_t smw[];
    uint32_t* Qa = smw;
    uint32_t* Kb = smw + 2304;
    uint32_t* Vb = smw + 10752;
    float* smax = (float*)(smw + 19968);
    float* ssum = smax + 128;
    float* ctxred = (float*)(smw + 2304);

    int z = blockIdx.x;
    int bh = z >> 2, qt = z & 3;
    int b = bh >> 3, h = bh & 7;
    int tid = threadIdx.x, wid = tid >> 5, lane = tid & 31;
    int mt = wid >> 1, half = wid & 1;
    int group = lane >> 2, tig = lane & 3;

    const uint32_t* qsrc = g_qh_h + ((size_t)bh * S_ + qt * 64) * 32;   // [s][kw]
    const uint32_t* ksrc = g_kh_h + (size_t)bh * 32 * S_;               // [kp][s]
    const float*    vsrc = g_vh   + (size_t)bh * 16384;                 // [s][dk] fp32

    // ---- stage Q: pure copy, 2048 words
    {
        int m = tid >> 2, wq = (tid & 3) * 8;
        uint4 u0 = *(const uint4*)(qsrc + m * 32 + wq);
        uint4 u1 = *(const uint4*)(qsrc + m * 32 + wq + 4);
        *(uint4*)&Qa[m * 36 + wq]     = u0;
        *(uint4*)&Qa[m * 36 + wq + 4] = u1;
    }
    // ---- stage K: pure copy, 8192 words
#pragma unroll
    for (int j = 0; j < 8; j++) {
        int lin = (tid + 256 * j) * 4;
        int kp2 = lin >> 8, s = lin & 255;
        uint4 u = *(const uint4*)(ksrc + kp2 * 256 + s);
        *(uint4*)&Kb[kp2 * 264 + s] = u;
    }
    // ---- stage V^T with cvt (fp32 -> packed s-pairs)
#pragma unroll
    for (int j = 0; j < 8; j++) {
        int lin = tid + 256 * j;
        int kp2 = lin >> 4, nq = (lin & 15) * 4;
        float4 r0 = *(const float4*)(vsrc + (size_t)(2 * kp2) * DK_ + nq);
        float4 r1 = *(const float4*)(vsrc + (size_t)(2 * kp2 + 1) * DK_ + nq);
        uint4 w4 = make_uint4(f2h2(r0.x, r1.x), f2h2(r0.y, r1.y),
                              f2h2(r0.z, r1.z), f2h2(r0.w, r1.w));
        *(uint4*)&Vb[kp2 * 72 + nq] = w4;
    }
    __syncthreads();

    // ---- GEMM1
    float sc[16][4] = {};
    const int m0 = mt * 16;
#pragma unroll
    for (int ks = 0; ks < 4; ks++) {
        uint32_t af[4];
        af[0] = Qa[(m0 + group) * 36 + ks * 8 + tig];
        af[1] = Qa[(m0 + group + 8) * 36 + ks * 8 + tig];
        af[2] = Qa[(m0 + group) * 36 + ks * 8 + tig + 4];
        af[3] = Qa[(m0 + group + 8) * 36 + ks * 8 + tig + 4];
#pragma unroll
        for (int nt = 0; nt < 16; nt++) {
            int n = half * 128 + nt * 8 + group;
            uint32_t bf[2];
            bf[0] = Kb[(ks * 8 + tig) * 264 + n];
            bf[1] = Kb[(ks * 8 + tig + 4) * 264 + n];
            mma_f16(sc[nt], af, bf);
        }
    }

    // ---- mask + scale
    const int rbase = qt * 64 + mt * 16;
#pragma unroll
    for (int nt = 0; nt < 16; nt++) {
        int col = half * 128 + nt * 8 + 2 * tig;
        int2 mr0 = *(const int2*)&mask[(rbase + group) * S_ + col];
        int2 mr1 = *(const int2*)&mask[(rbase + group + 8) * S_ + col];
        sc[nt][0] = mr0.x ? sc[nt][0] * 0.125f : -1e9f;
        sc[nt][1] = mr0.y ? sc[nt][1] * 0.125f : -1e9f;
        sc[nt][2] = mr1.x ? sc[nt][2] * 0.125f : -1e9f;
        sc[nt][3] = mr1.y ? sc[nt][3] * 0.125f : -1e9f;
    }

    __syncthreads();   // Kb dead; smax/ctxred traffic begins

    // ---- softmax
    float mx0 = -3.0e38f, mx1 = -3.0e38f;
#pragma unroll
    for (int nt = 0; nt < 16; nt++) {
        mx0 = fmaxf(mx0, fmaxf(sc[nt][0], sc[nt][1]));
        mx1 = fmaxf(mx1, fmaxf(sc[nt][2], sc[nt][3]));
    }
#pragma unroll
    for (int off = 1; off < 4; off <<= 1) {
        mx0 = fmaxf(mx0, __shfl_xor_sync(0xffffffffu, mx0, off));
        mx1 = fmaxf(mx1, __shfl_xor_sync(0xffffffffu, mx1, off));
    }
    if (tig == 0) {
        smax[(mt * 16 + group) * 2 + half]     = mx0;
        smax[(mt * 16 + group + 8) * 2 + half] = mx1;
    }
    __syncthreads();
    mx0 = fmaxf(smax[(mt * 16 + group) * 2],     smax[(mt * 16 + group) * 2 + 1]);
    mx1 = fmaxf(smax[(mt * 16 + group + 8) * 2], smax[(mt * 16 + group + 8) * 2 + 1]);

    float s0 = 0.0f, s1 = 0.0f;
#pragma unroll
    for (int nt = 0; nt < 16; nt++) {
        sc[nt][0] = __expf(sc[nt][0] - mx0); s0 += sc[nt][0];
        sc[nt][1] = __expf(sc[nt][1] - mx0); s0 += sc[nt][1];
        sc[nt][2] = __expf(sc[nt][2] - mx1); s1 += sc[nt][2];
        sc[nt][3] = __expf(sc[nt][3] - mx1); s1 += sc[nt][3];
    }
#pragma unroll
    for (int off = 1; off < 4; off <<= 1) {
        s0 += __shfl_xor_sync(0xffffffffu, s0, off);
        s1 += __shfl_xor_sync(0xffffffffu, s1, off);
    }
    if (tig == 0) {
        ssum[(mt * 16 + group) * 2 + half]     = s0;
        ssum[(mt * 16 + group + 8) * 2 + half] = s1;
    }
    __syncthreads();
    float inv0 = 1.0f / (ssum[(mt * 16 + group) * 2] + ssum[(mt * 16 + group) * 2 + 1]);
    float inv1 = 1.0f / (ssum[(mt * 16 + group + 8) * 2] + ssum[(mt * 16 + group + 8) * 2 + 1]);
#pragma unroll
    for (int nt = 0; nt < 16; nt++) {
        sc[nt][0] *= inv0; sc[nt][1] *= inv0;
        sc[nt][2] *= inv1; sc[nt][3] *= inv1;
    }

    // ---- GEMM2
    float ca[8][4] = {};
#pragma unroll
    for (int ks2 = 0; ks2 < 8; ks2++) {
        uint32_t af[4];
        af[0] = f2h2(sc[2 * ks2][0],     sc[2 * ks2][1]);
        af[1] = f2h2(sc[2 * ks2][2],     sc[2 * ks2][3]);
        af[2] = f2h2(sc[2 * ks2 + 1][0], sc[2 * ks2 + 1][1]);
        af[3] = f2h2(sc[2 * ks2 + 1][2], sc[2 * ks2 + 1][3]);
        int kpb = half * 64 + ks2 * 8;
#pragma unroll
        for (int nt2 = 0; nt2 < 8; nt2++) {
            uint32_t bf[2];
            bf[0] = Vb[(kpb + tig) * 72 + nt2 * 8 + group];
            bf[1] = Vb[(kpb + tig + 4) * 72 + nt2 * 8 + group];
            mma_f16(ca[nt2], af, bf);
        }
    }

    // ---- cross-half reduce + fp16 ctx write
    float* cr = ctxred + mt * 16 * 65;
    if (half == 0) {
#pragma unroll
        for (int nt2 = 0; nt2 < 8; nt2++) {
            int c0 = nt2 * 8 + 2 * tig;
            cr[group * 65 + c0]           = ca[nt2][0];
            cr[group * 65 + c0 + 1]       = ca[nt2][1];
            cr[(group + 8) * 65 + c0]     = ca[nt2][2];
            cr[(group + 8) * 65 + c0 + 1] = ca[nt2][3];
        }
    }
    __syncthreads();
    if (half == 1) {
#pragma unroll
        for (int nt2 = 0; nt2 < 8; nt2++) {
            int c0 = nt2 * 8 + 2 * tig;
            float v0 = ca[nt2][0] + cr[group * 65 + c0];
            float v1 = ca[nt2][1] + cr[group * 65 + c0 + 1];
            float v2 = ca[nt2][2] + cr[(group + 8) * 65 + c0];
            float v3 = ca[nt2][3] + cr[(group + 8) * 65 + c0 + 1];
            int cw = (h * DK_ + c0) >> 1;
            g_ctx_h[((size_t)b * S_ + rbase + group) * 256 + cw]     = f2h2(v0, v1);
            g_ctx_h[((size_t)b * S_ + rbase + group + 8) * 256 + cw] = f2h2(v2, v3);
        }
    }
}

// ---------------- launch ----------------
extern "C" void kernel_launch(void* const* d_in, const int* in_sizes, int n_in,
                              void* d_out, int out_size) {
    const float* q    = (const float*)d_in[0];
    const float* k    = (const float*)d_in[1];
    const float* v    = (const float*)d_in[2];
    const int*   mask = (const int*)  d_in[3];
    const float* wg   = (const float*)d_in[4];
    const float* wn   = (const float*)d_in[5];
    const float* wq   = (const float*)d_in[6];
    const float* bq   = (const float*)d_in[7];
    const float* wk   = (const float*)d_in[8];
    const float* bk   = (const float*)d_in[9];
    const float* wv   = (const float*)d_in[10];
    const float* bv   = (const float*)d_in[11];
    const float* wo   = (const float*)d_in[12];
    const float* bo   = (const float*)d_in[13];
    float* out = (float*)d_out;

    cudaFuncSetAttribute(fused_attn_kernel,
                         cudaFuncAttributeMaxDynamicSharedMemorySize, ATTN_SMEM_BYTES);
    cudaFuncSetAttribute(proj_mma,
                         cudaFuncAttributeMaxDynamicSharedMemorySize, MMA_SMEM_BYTES);
    cudaFuncSetAttribute(final_mma,
                         cudaFuncAttributeMaxDynamicSharedMemorySize, MMA_SMEM_BYTES);

    xsum_kernel<<<B_, 512>>>(q);
    gating_kernel<<<1, 1024>>>(wg, wn, out, out_size);
    proj_mma<<<dim3(4, 2, B_ * 3), 256, MMA_SMEM_BYTES>>>(q, k, v, wq, wk, wv, bq, bk, bv);
    fused_attn_kernel<<<B_ * H_ * 4, 256, ATTN_SMEM_BYTES>>>(mask);
    final_mma<<<dim3(4, 2, B_), 256, MMA_SMEM_BYTES>>>(wo, bo, out);
}